// round 11
// baseline (speedup 1.0000x reference)
#include <cuda_runtime.h>
#include <math.h>
#include <stdint.h>

#define NSEQ 2048
#define DIM  1024
#define HEADS 16
#define QKV6 6144
#define HSLL ((long long)NSEQ * NSEQ)

typedef unsigned short bf16;

// ---------------- device scratch (allocation-free) ----------------
__device__ bf16 g_xh[NSEQ * DIM];
__device__ bf16 g_xl[NSEQ * DIM];
__device__ bf16 g_wqh[QKV6 * DIM];
__device__ bf16 g_wql[QKV6 * DIM];
__device__ bf16 g_woh[DIM * DIM];
__device__ bf16 g_wol[DIM * DIM];
__device__ bf16 g_qh[NSEQ * QKV6];
__device__ bf16 g_ql[NSEQ * QKV6];
__device__ bf16 g_vth[DIM * NSEQ];   // vc transposed: [h*64+d][n]
__device__ bf16 g_vtl[DIM * NSEQ];
__device__ bf16 g_t1h[(size_t)HEADS * NSEQ * NSEQ];
__device__ bf16 g_t1l[(size_t)HEADS * NSEQ * NSEQ];
__device__ bf16 g_sgh[(size_t)HEADS * NSEQ * NSEQ];
__device__ bf16 g_sgl[(size_t)HEADS * NSEQ * NSEQ];
__device__ float g_sc[(size_t)HEADS * NSEQ * NSEQ];
__device__ float g_su[(size_t)HEADS * NSEQ * NSEQ];
__device__ bf16 g_ah[(size_t)HEADS * NSEQ * NSEQ];
__device__ bf16 g_al[(size_t)HEADS * NSEQ * NSEQ];
__device__ bf16 g_oh[NSEQ * DIM];
__device__ bf16 g_ol[NSEQ * DIM];

// ---------------- helpers ----------------
__device__ __forceinline__ bf16 f2bf(float f) {
    bf16 h;
    asm("cvt.rn.bf16.f32 %0, %1;" : "=h"(h) : "f"(f));
    return h;
}
__device__ __forceinline__ float bf2f(bf16 h) {
    return __uint_as_float(((unsigned int)h) << 16);
}

__device__ __forceinline__ uint32_t smem_u32(const void* p) {
    uint32_t a;
    asm("{ .reg .u64 t; cvta.to.shared.u64 t, %1; cvt.u32.u64 %0, t; }" : "=r"(a) : "l"(p));
    return a;
}

__device__ __forceinline__ void cpa16(uint32_t saddr, const void* g) {
    asm volatile("cp.async.ca.shared.global [%0], [%1], 16;" :: "r"(saddr), "l"(g));
}
#define CP_COMMIT() asm volatile("cp.async.commit_group;" ::: "memory")
#define CP_WAIT0() asm volatile("cp.async.wait_group 0;" ::: "memory")
#define CP_WAIT1() asm volatile("cp.async.wait_group 1;" ::: "memory")

__device__ __forceinline__ void ldm4(uint32_t* r, uint32_t addr) {
    asm volatile("ldmatrix.sync.aligned.m8n8.x4.shared.b16 {%0,%1,%2,%3}, [%4];"
        : "=r"(r[0]), "=r"(r[1]), "=r"(r[2]), "=r"(r[3]) : "r"(addr));
}

__device__ __forceinline__ void mma16816(float* d, const uint32_t* a, const uint32_t* b) {
    asm volatile(
        "mma.sync.aligned.m16n8k16.row.col.f32.bf16.bf16.f32 "
        "{%0,%1,%2,%3}, {%4,%5,%6,%7}, {%8,%9}, {%0,%1,%2,%3};"
        : "+f"(d[0]), "+f"(d[1]), "+f"(d[2]), "+f"(d[3])
        : "r"(a[0]), "r"(a[1]), "r"(a[2]), "r"(a[3]), "r"(b[0]), "r"(b[1]));
}

// SW128 swizzle for 128-byte rows: XOR bits[6:4] with row bits[2:0]
__device__ __forceinline__ uint32_t sw128(uint32_t off) {
    return off ^ ((off >> 3) & 0x70);
}

// ---------------- warp-MMA GEMM engine ----------------
// bf16x3 split; rows are 128B: [32 bf16 hi | 32 bf16 lo]; SW128.
// cp.async 2-stage (R7 ordering), BK=32. B fragments loaded pairwise via ldmatrix.x4.
// C[i0+m][n0+n] = sum_k A[m][k]*B[n][k]
// epi: 0 fp32; 1 qkv-scale + split; 2 mask j<=i + split; 3 sigmoid strict-upper + split;
//      4 split; 5 fp32 = acc - Rf[idx]; 6 fp32 = silu(acc).
// skipm: 1 skip n0>i0; 2 skip n0<i0. trik: 1 -> k in [n0, i0+128); 2 -> k in [0, i0+128).
template<int BN, int WMC>
__global__ void __launch_bounds__(256, 2) mma_gemm(
    const bf16* __restrict__ Ah, const bf16* __restrict__ Al, int lda, long long sA,
    const bf16* __restrict__ Bh, const bf16* __restrict__ Bl, int ldb, long long sB,
    float* Cf, bf16* Ch, bf16* Cl, const float* Rf, int ldc, long long sC,
    int K, int epi, int skipm, int trik)
{
    constexpr int WNC = 8 / WMC;
    constexpr int WM = 128 / WMC;
    constexpr int WN = BN / WNC;
    constexpr int MF = WM / 16;
    constexpr int NF = WN / 8;
    // stage layout: A 128 rows x 128B = 16KB, B BN rows x 128B
    constexpr int S_A = 0;
    constexpr int S_B = 16384;
    constexpr int STG = 16384 + BN * 128;

    int i0 = blockIdx.y * 128;
    int n0 = blockIdx.x * BN;
    if (skipm == 1 && n0 > i0) return;
    if (skipm == 2 && n0 < i0) return;
    int z = blockIdx.z;
    Ah += (long long)z * sA;
    Al += (long long)z * sA;
    Bh += (long long)z * sB;
    Bl += (long long)z * sB;
    if (Cf) Cf += (long long)z * sC;
    if (Rf) Rf += (long long)z * sC;
    if (Ch) {
        Ch += (long long)z * sC;
        Cl += (long long)z * sC;
    }

    int kbeg = 0;
    int kend = K;
    if (trik == 1) {
        kbeg = n0;
        kend = i0 + 128;
        if (kend > K) kend = K;
    } else if (trik == 2) {
        kend = i0 + 128;
        if (kend > K) kend = K;
    }
    int nch = (kend - kbeg + 31) >> 5;

    extern __shared__ __align__(1024) char smem[];
    uint32_t sb = smem_u32(smem);
    int tid = threadIdx.x;
    int wid = tid >> 5;
    int lane = tid & 31;
    int wm = wid % WMC;
    int wn = wid / WMC;

    auto stage_chunk = [&](int buf, int kt) {
        uint32_t base = sb + buf * STG;
        for (int u = tid; u < 512; u += 256) {
            int r = u >> 2;
            int kb = u & 3;
            long long go = (long long)(i0 + r) * lda + kt + kb * 8;
            uint32_t off = ((uint32_t)r << 7) | ((uint32_t)kb << 4);
            cpa16(base + S_A + sw128(off), Ah + go);
            cpa16(base + S_A + sw128(off + 64), Al + go);
        }
        for (int u = tid; u < BN * 4; u += 256) {
            int r = u >> 2;
            int kb = u & 3;
            long long go = (long long)(n0 + r) * ldb + kt + kb * 8;
            uint32_t off = ((uint32_t)r << 7) | ((uint32_t)kb << 4);
            cpa16(base + S_B + sw128(off), Bh + go);
            cpa16(base + S_B + sw128(off + 64), Bl + go);
        }
    };

    float acc[MF][NF][4];
    #pragma unroll
    for (int a = 0; a < MF; a++)
        #pragma unroll
        for (int b = 0; b < NF; b++)
            #pragma unroll
            for (int c = 0; c < 4; c++)
                acc[a][b][c] = 0.f;

    stage_chunk(0, kbeg);
    CP_COMMIT();

    for (int t = 0; t < nch; t++) {
        if (t + 1 < nch) {
            stage_chunk((t + 1) & 1, kbeg + (t + 1) * 32);
            CP_COMMIT();
            CP_WAIT1();
        } else {
            CP_WAIT0();
        }
        __syncthreads();

        uint32_t cbase = sb + (t & 1) * STG;
        #pragma unroll
        for (int ks = 0; ks < 2; ks++) {
            int g = lane >> 3;
            int rowin = lane & 7;
            // A fragments: x4 per mf (16m x 16k), hi and lo
            int kbA = ks * 32 + (g >> 1) * 16;
            uint32_t ahf[MF][4], alf[MF][4];
            #pragma unroll
            for (int mf = 0; mf < MF; mf++) {
                int r = wm * WM + mf * 16 + (g & 1) * 8 + rowin;
                uint32_t off = ((uint32_t)r << 7) + (uint32_t)kbA;
                ldm4(ahf[mf], cbase + S_A + sw128(off));
                ldm4(alf[mf], cbase + S_A + sw128(off + 64));
            }
            // B fragments: x4 loads a PAIR of n8 tiles (nf, nf+1)
            int kbB = ks * 32 + ((lane >> 3) & 1) * 16;
            int rowB = ((lane >> 4) & 1) * 8 + rowin;
            uint32_t bhf[NF][2], blf[NF][2];
            #pragma unroll
            for (int nfp = 0; nfp < NF; nfp += 2) {
                int r = wn * WN + nfp * 8 + rowB;
                uint32_t off = ((uint32_t)r << 7) + (uint32_t)kbB;
                uint32_t q[4];
                ldm4(q, cbase + S_B + sw128(off));
                bhf[nfp][0] = q[0]; bhf[nfp][1] = q[1];
                bhf[nfp + 1][0] = q[2]; bhf[nfp + 1][1] = q[3];
                ldm4(q, cbase + S_B + sw128(off + 64));
                blf[nfp][0] = q[0]; blf[nfp][1] = q[1];
                blf[nfp + 1][0] = q[2]; blf[nfp + 1][1] = q[3];
            }
            #pragma unroll
            for (int mf = 0; mf < MF; mf++) {
                #pragma unroll
                for (int nf = 0; nf < NF; nf++) {
                    mma16816(acc[mf][nf], ahf[mf], bhf[nf]);
                    mma16816(acc[mf][nf], ahf[mf], blf[nf]);
                    mma16816(acc[mf][nf], alf[mf], bhf[nf]);
                }
            }
        }
        __syncthreads();
    }

    // epilogue from register fragments (vectorized 2-column stores)
    int crow = lane >> 2;
    int ccol = (lane & 3) * 2;
    #pragma unroll
    for (int mf = 0; mf < MF; mf++) {
        #pragma unroll
        for (int nf = 0; nf < NF; nf++) {
            #pragma unroll
            for (int c2 = 0; c2 < 2; c2++) {
                int gi = i0 + wm * WM + mf * 16 + crow + c2 * 8;
                int gj = n0 + wn * WN + nf * 8 + ccol;
                float v0 = acc[mf][nf][c2 * 2];
                float v1 = acc[mf][nf][c2 * 2 + 1];
                long long idx = (long long)gi * ldc + gj;
                if (epi == 0) {
                    float2 f2;
                    f2.x = v0;
                    f2.y = v1;
                    *(float2*)(Cf + idx) = f2;
                } else if (epi == 5) {
                    // scores = Sc - silu(Su): Rf holds silu(Su)
                    float2 r2 = *(const float2*)(Rf + idx);
                    float2 f2;
                    f2.x = v0 - r2.x;
                    f2.y = v1 - r2.y;
                    *(float2*)(Cf + idx) = f2;
                } else if (epi == 6) {
                    // silu(Su)
                    float2 f2;
                    f2.x = v0 / (1.f + expf(-v0));
                    f2.y = v1 / (1.f + expf(-v1));
                    *(float2*)(Cf + idx) = f2;
                } else {
                    if (epi == 1) {
                        int c0 = gj >> 10;
                        int c1 = (gj + 1) >> 10;
                        if (c0 == 0 || c0 == 3) v0 *= 0.125f;
                        if (c1 == 0 || c1 == 3) v1 *= 0.125f;
                    } else if (epi == 2) {
                        v0 = (gj <= gi) ? v0 : 0.f;
                        v1 = (gj + 1 <= gi) ? v1 : 0.f;
                    } else if (epi == 3) {
                        v0 = (gj > gi) ? (1.f / (1.f + expf(-v0))) : 0.f;
                        v1 = (gj + 1 > gi) ? (1.f / (1.f + expf(-v1))) : 0.f;
                    }
                    bf16 h0 = f2bf(v0);
                    bf16 h1 = f2bf(v1);
                    uint32_t hp = (uint32_t)h0 | ((uint32_t)h1 << 16);
                    uint32_t lp = (uint32_t)f2bf(v0 - bf2f(h0)) | ((uint32_t)f2bf(v1 - bf2f(h1)) << 16);
                    *(uint32_t*)(Ch + idx) = hp;
                    *(uint32_t*)(Cl + idx) = lp;
                }
            }
        }
    }
}

// ---------------- split fp32 -> (hi, lo) bf16 ----------------
__global__ void split_kernel(const float* __restrict__ s, bf16* __restrict__ h,
                             bf16* __restrict__ l, int n4)
{
    int i = blockIdx.x * 256 + threadIdx.x;
    if (i < n4) {
        float4 v = ((const float4*)s)[i];
        float vv[4];
        vv[0] = v.x; vv[1] = v.y; vv[2] = v.z; vv[3] = v.w;
        for (int k = 0; k < 4; k++) {
            bf16 hh = f2bf(vv[k]);
            h[i * 4 + k] = hh;
            l[i * 4 + k] = f2bf(vv[k] - bf2f(hh));
        }
    }
}

// ---------------- transpose vc: [n][5120 + c] -> [c][n] ----------------
__global__ void transpose_vc(const bf16* __restrict__ qh, const bf16* __restrict__ ql,
                             bf16* __restrict__ vth, bf16* __restrict__ vtl)
{
    __shared__ bf16 th[32][33];
    __shared__ bf16 tl[32][33];
    int c0 = blockIdx.x * 32;
    int n0 = blockIdx.y * 32;
    int tx = threadIdx.x;
    int ty = threadIdx.y;
    for (int r = ty; r < 32; r += 8) {
        th[r][tx] = qh[(long long)(n0 + r) * QKV6 + 5120 + c0 + tx];
        tl[r][tx] = ql[(long long)(n0 + r) * QKV6 + 5120 + c0 + tx];
    }
    __syncthreads();
    for (int r = ty; r < 32; r += 8) {
        vth[(long long)(c0 + r) * NSEQ + n0 + tx] = th[tx][r];
        vtl[(long long)(c0 + r) * NSEQ + n0 + tx] = tl[tx][r];
    }
}

// ---------------- softmax over scores (j<=i) -> attn bf16 pair ----------------
__global__ void softmax_kernel(const float* __restrict__ sc,
                               bf16* __restrict__ ah, bf16* __restrict__ al, int n)
{
    int i = blockIdx.x;
    int hh = blockIdx.y;
    long long base = ((long long)hh * n + i) * (long long)n;
    const float* scr = sc + base;
    bf16* ahr = ah + base;
    bf16* alr = al + base;

    int tid = threadIdx.x;
    const int NT = 256;
    float vals[8];
    int cnt = 0;
    float lmax = -INFINITY;
    for (int j = tid; j <= i; j += NT) {
        float s = scr[j];
        vals[cnt] = s;
        cnt++;
        lmax = fmaxf(lmax, s);
    }

    __shared__ float red[33];
    for (int o = 16; o > 0; o >>= 1) lmax = fmaxf(lmax, __shfl_xor_sync(0xffffffffu, lmax, o));
    if ((tid & 31) == 0) red[tid >> 5] = lmax;
    __syncthreads();
    if (tid == 0) {
        float m0 = red[0];
        for (int w = 1; w < NT / 32; w++) m0 = fmaxf(m0, red[w]);
        red[32] = m0;
    }
    __syncthreads();
    float m = red[32];
    __syncthreads();

    float lsum = 0.f;
    for (int c = 0; c < cnt; c++) {
        float e = expf(vals[c] - m);
        vals[c] = e;
        lsum += e;
    }
    for (int o = 16; o > 0; o >>= 1) lsum += __shfl_xor_sync(0xffffffffu, lsum, o);
    if ((tid & 31) == 0) red[tid >> 5] = lsum;
    __syncthreads();
    if (tid == 0) {
        float s0 = 0.f;
        for (int w = 0; w < NT / 32; w++) s0 += red[w];
        red[32] = s0;
    }
    __syncthreads();
    float inv = 1.f / red[32];

    cnt = 0;
    for (int j = tid; j <= i; j += NT) {
        float v = vals[cnt] * inv;
        cnt++;
        bf16 vh = f2bf(v);
        ahr[j] = vh;
        alr[j] = f2bf(v - bf2f(vh));
    }
    int jend = (((i >> 7) + 1) << 7);
    for (int j = i + 1 + tid; j < jend; j += NT) {
        ahr[j] = 0;
        alr[j] = 0;
    }
}

extern "C" void kernel_launch(void* const* d_in, const int* in_sizes, int n_in,
                              void* d_out, int out_size)
{
    const float* x     = (const float*)d_in[0];
    const float* w_qkv = (const float*)d_in[1];
    const float* w_out = (const float*)d_in[2];
    float* out = (float*)d_out;

    bf16 *xh, *xl, *wqh, *wql, *woh, *wol, *qh, *ql, *vth, *vtl;
    bf16 *t1h, *t1l, *sgh, *sgl, *ah, *al, *oh, *ol;
    float *sc, *su;
    cudaGetSymbolAddress((void**)&xh, g_xh);
    cudaGetSymbolAddress((void**)&xl, g_xl);
    cudaGetSymbolAddress((void**)&wqh, g_wqh);
    cudaGetSymbolAddress((void**)&wql, g_wql);
    cudaGetSymbolAddress((void**)&woh, g_woh);
    cudaGetSymbolAddress((void**)&wol, g_wol);
    cudaGetSymbolAddress((void**)&qh, g_qh);
    cudaGetSymbolAddress((void**)&ql, g_ql);
    cudaGetSymbolAddress((void**)&vth, g_vth);
    cudaGetSymbolAddress((void**)&vtl, g_vtl);
    cudaGetSymbolAddress((void**)&t1h, g_t1h);
    cudaGetSymbolAddress((void**)&t1l, g_t1l);
    cudaGetSymbolAddress((void**)&sgh, g_sgh);
    cudaGetSymbolAddress((void**)&sgl, g_sgl);
    cudaGetSymbolAddress((void**)&sc, g_sc);
    cudaGetSymbolAddress((void**)&su, g_su);
    cudaGetSymbolAddress((void**)&ah, g_ah);
    cudaGetSymbolAddress((void**)&al, g_al);
    cudaGetSymbolAddress((void**)&oh, g_oh);
    cudaGetSymbolAddress((void**)&ol, g_ol);

    const int SMT128 = 2 * (16384 + 128 * 128);  // 65536
    const int SMT64  = 2 * (16384 + 64 * 128);   // 49152
    cudaFuncSetAttribute(mma_gemm<128, 2>, cudaFuncAttributeMaxDynamicSharedMemorySize, SMT128);
    cudaFuncSetAttribute(mma_gemm<64, 4>, cudaFuncAttributeMaxDynamicSharedMemorySize, SMT64);

    // splits
    {
        int n4 = NSEQ * DIM / 4;
        split_kernel<<<(n4 + 255) / 256, 256>>>(x, xh, xl, n4);
        n4 = QKV6 * DIM / 4;
        split_kernel<<<(n4 + 255) / 256, 256>>>(w_qkv, wqh, wql, n4);
        n4 = DIM * DIM / 4;
        split_kernel<<<(n4 + 255) / 256, 256>>>(w_out, woh, wol, n4);
    }

    // 1) qkvs = x @ w_qkv^T (scale qu,qc by 0.125), split pair
    mma_gemm<128, 2><<<dim3(QKV6 / 128, NSEQ / 128, 1), 256, SMT128>>>(
        xh, xl, DIM, 0, wqh, wql, DIM, 0,
        (float*)0, qh, ql, (const float*)0, QKV6, 0,
        DIM, 1, 0, 0);

    // 1b) transpose vc -> [64][N] per head
    transpose_vc<<<dim3(DIM / 32, NSEQ / 32), dim3(32, 8)>>>(qh, ql, vth, vtl);

    // component offsets: qu=0, ku=1024, vu=2048, qc=3072, kc=4096, vc=5120
    // 2) term1 = qc @ vu^T, lower incl diag
    mma_gemm<128, 2><<<dim3(16, 16, HEADS), 256, SMT128>>>(
        qh + 3072, ql + 3072, QKV6, 64, qh + 2048, ql + 2048, QKV6, 64,
        (float*)0, t1h, t1l, (const float*)0, NSEQ, HSLL,
        64, 2, 1, 0);

    // 3) sig = sigmoid(qu @ ku^T), strict upper
    mma_gemm<128, 2><<<dim3(16, 16, HEADS), 256, SMT128>>>(
        qh + 0, ql + 0, QKV6, 64, qh + 1024, ql + 1024, QKV6, 64,
        (float*)0, sgh, sgl, (const float*)0, NSEQ, HSLL,
        64, 3, 2, 0);

    // 4) su = silu(term1 @ sig^T), triangular k-range (epi 6)
    mma_gemm<128, 2><<<dim3(16, 16, HEADS), 256, SMT128>>>(
        t1h, t1l, NSEQ, HSLL, sgh, sgl, NSEQ, HSLL,
        su, (bf16*)0, (bf16*)0, (const float*)0, NSEQ, HSLL,
        NSEQ, 6, 1, 1);

    // 5) scores = qc @ kc^T - su (lower tiles only, epi 5)
    mma_gemm<128, 2><<<dim3(16, 16, HEADS), 256, SMT128>>>(
        qh + 3072, ql + 3072, QKV6, 64, qh + 4096, ql + 4096, QKV6, 64,
        sc, (bf16*)0, (bf16*)0, su, NSEQ, HSLL,
        64, 5, 1, 0);

    // 6) softmax -> attn split pair
    softmax_kernel<<<dim3(NSEQ, HEADS), 256>>>(sc, ah, al, NSEQ);

    // 7) o[:, h*64:(h+1)*64] = attn_h @ vcT_h (causal k-range)
    mma_gemm<64, 4><<<dim3(1, 16, HEADS), 256, SMT64>>>(
        ah, al, NSEQ, HSLL, vth, vtl, NSEQ, 64LL * NSEQ,
        (float*)0, oh, ol, (const float*)0, HEADS * 64, 64,
        NSEQ, 4, 0, 2);

    // 8) out = o @ w_out^T, fp32
    mma_gemm<128, 2><<<dim3(DIM / 128, NSEQ / 128, 1), 256, SMT128>>>(
        oh, ol, HEADS * 64, 0, woh, wol, HEADS * 64, 0,
        out, (bf16*)0, (bf16*)0, (const float*)0, DIM, 0,
        HEADS * 64, 0, 0, 0);
}

// round 12
// speedup vs baseline: 1.1293x; 1.1293x over previous
#include <cuda_runtime.h>
#include <math.h>
#include <stdint.h>

#define NSEQ 2048
#define DIM  1024
#define HEADS 16
#define QKV6 6144
#define HSLL ((long long)NSEQ * NSEQ)

typedef unsigned short bf16;

// ---------------- device scratch (allocation-free) ----------------
__device__ bf16 g_xh[NSEQ * DIM];
__device__ bf16 g_xl[NSEQ * DIM];
__device__ bf16 g_wqh[QKV6 * DIM];
__device__ bf16 g_wql[QKV6 * DIM];
__device__ bf16 g_woh[DIM * DIM];
__device__ bf16 g_wol[DIM * DIM];
__device__ bf16 g_qh[NSEQ * QKV6];
__device__ bf16 g_ql[NSEQ * QKV6];
__device__ bf16 g_vth[DIM * NSEQ];   // vc transposed: [h*64+d][n]
__device__ bf16 g_vtl[DIM * NSEQ];
__device__ bf16 g_t1h[(size_t)HEADS * NSEQ * NSEQ];
__device__ bf16 g_t1l[(size_t)HEADS * NSEQ * NSEQ];
__device__ bf16 g_sgh[(size_t)HEADS * NSEQ * NSEQ];
__device__ bf16 g_sgl[(size_t)HEADS * NSEQ * NSEQ];
__device__ float g_sc[(size_t)HEADS * NSEQ * NSEQ];
__device__ float g_su[(size_t)HEADS * NSEQ * NSEQ];
__device__ bf16 g_ah[(size_t)HEADS * NSEQ * NSEQ];
__device__ bf16 g_al[(size_t)HEADS * NSEQ * NSEQ];
__device__ bf16 g_oh[NSEQ * DIM];
__device__ bf16 g_ol[NSEQ * DIM];

// ---------------- helpers ----------------
__device__ __forceinline__ bf16 f2bf(float f) {
    bf16 h;
    asm("cvt.rn.bf16.f32 %0, %1;" : "=h"(h) : "f"(f));
    return h;
}
__device__ __forceinline__ float bf2f(bf16 h) {
    return __uint_as_float(((unsigned int)h) << 16);
}

__device__ __forceinline__ uint32_t smem_u32(const void* p) {
    uint32_t a;
    asm("{ .reg .u64 t; cvta.to.shared.u64 t, %1; cvt.u32.u64 %0, t; }" : "=r"(a) : "l"(p));
    return a;
}

__device__ __forceinline__ void cpa16(uint32_t saddr, const void* g) {
    asm volatile("cp.async.cg.shared.global [%0], [%1], 16;" :: "r"(saddr), "l"(g));
}
#define CP_COMMIT() asm volatile("cp.async.commit_group;" ::: "memory")
#define CP_WAIT0() asm volatile("cp.async.wait_group 0;" ::: "memory")
#define CP_WAIT1() asm volatile("cp.async.wait_group 1;" ::: "memory")

__device__ __forceinline__ void ldm4(uint32_t* r, uint32_t addr) {
    asm volatile("ldmatrix.sync.aligned.m8n8.x4.shared.b16 {%0,%1,%2,%3}, [%4];"
        : "=r"(r[0]), "=r"(r[1]), "=r"(r[2]), "=r"(r[3]) : "r"(addr));
}

__device__ __forceinline__ void mma16816(float* d, const uint32_t* a, const uint32_t* b) {
    asm volatile(
        "mma.sync.aligned.m16n8k16.row.col.f32.bf16.bf16.f32 "
        "{%0,%1,%2,%3}, {%4,%5,%6,%7}, {%8,%9}, {%0,%1,%2,%3};"
        : "+f"(d[0]), "+f"(d[1]), "+f"(d[2]), "+f"(d[3])
        : "r"(a[0]), "r"(a[1]), "r"(a[2]), "r"(a[3]), "r"(b[0]), "r"(b[1]));
}

// SW128 swizzle for 128-byte rows: XOR bits[6:4] with row bits[2:0]
__device__ __forceinline__ uint32_t sw128(uint32_t off) {
    return off ^ ((off >> 3) & 0x70);
}

// ---------------- warp-MMA GEMM engine ----------------
// bf16x3 split; rows are 128B: [32 bf16 hi | 32 bf16 lo]; SW128.
// cp.async 2-stage (R7 ordering), BK=32. B fragments loaded pairwise via ldmatrix.x4.
// C[i0+m][n0+n] = sum_k A[m][k]*B[n][k]
// epi: 0 fp32; 1 qkv-scale + split; 2 mask j<=i + split; 3 sigmoid strict-upper + split; 4 split.
// skipm: 1 skip n0>i0; 2 skip n0<i0. trik: 1 -> k in [n0, i0+128); 2 -> k in [0, i0+128).
// fuse3: z = h*3+comp; comp0=term1 (A qc, B vu, epi2), comp1=sig (A qu, B ku, epi3),
//        comp2=Sc (A qc, B kc, epi0). Ah/Bh bases are qh; outputs Ch/Cl=t1, Ch2/Cl2=sg, Cf=sc.
template<int BN, int WMC>
__global__ void __launch_bounds__(256, 2) mma_gemm(
    const bf16* __restrict__ Ah, const bf16* __restrict__ Al, int lda, long long sA,
    const bf16* __restrict__ Bh, const bf16* __restrict__ Bl, int ldb, long long sB,
    float* Cf, bf16* Ch, bf16* Cl, bf16* Ch2, bf16* Cl2, int ldc, long long sC,
    int K, int epi, int skipm, int trik, int fuse3)
{
    constexpr int WNC = 8 / WMC;
    constexpr int WM = 128 / WMC;
    constexpr int WN = BN / WNC;
    constexpr int MF = WM / 16;
    constexpr int NF = WN / 8;
    // stage layout: A 128 rows x 128B = 16KB, B BN rows x 128B
    constexpr int S_A = 0;
    constexpr int S_B = 16384;
    constexpr int STG = 16384 + BN * 128;

    int i0 = blockIdx.y * 128;
    int n0 = blockIdx.x * BN;
    int z = blockIdx.z;

    if (fuse3) {
        int comp = z % 3;
        int h = z / 3;
        skipm = (comp == 1) ? 2 : 1;
        epi = (comp == 0) ? 2 : ((comp == 1) ? 3 : 0);
        if (skipm == 1 && n0 > i0) return;
        if (skipm == 2 && n0 < i0) return;
        int aoff = (comp == 1) ? 0 : 3072;
        int boff = (comp == 0) ? 2048 : ((comp == 1) ? 1024 : 4096);
        Ah += h * 64 + aoff;
        Al += h * 64 + aoff;
        Bh += h * 64 + boff;
        Bl += h * 64 + boff;
        long long hs = (long long)h * HSLL;
        if (comp == 2) {
            Cf += hs;
        } else if (comp == 0) {
            Ch += hs;
            Cl += hs;
        } else {
            Ch = Ch2 + hs;
            Cl = Cl2 + hs;
        }
    } else {
        if (skipm == 1 && n0 > i0) return;
        if (skipm == 2 && n0 < i0) return;
        Ah += (long long)z * sA;
        Al += (long long)z * sA;
        Bh += (long long)z * sB;
        Bl += (long long)z * sB;
        if (Cf) Cf += (long long)z * sC;
        if (Ch) {
            Ch += (long long)z * sC;
            Cl += (long long)z * sC;
        }
    }

    int kbeg = 0;
    int kend = K;
    if (trik == 1) {
        kbeg = n0;
        kend = i0 + 128;
        if (kend > K) kend = K;
    } else if (trik == 2) {
        kend = i0 + 128;
        if (kend > K) kend = K;
    }
    int nch = (kend - kbeg + 31) >> 5;

    extern __shared__ __align__(1024) char smem[];
    uint32_t sb = smem_u32(smem);
    int tid = threadIdx.x;
    int wid = tid >> 5;
    int lane = tid & 31;
    int wm = wid % WMC;
    int wn = wid / WMC;

    auto stage_chunk = [&](int buf, int kt) {
        uint32_t base = sb + buf * STG;
        for (int u = tid; u < 512; u += 256) {
            int r = u >> 2;
            int kb = u & 3;
            long long go = (long long)(i0 + r) * lda + kt + kb * 8;
            uint32_t off = ((uint32_t)r << 7) | ((uint32_t)kb << 4);
            cpa16(base + S_A + sw128(off), Ah + go);
            cpa16(base + S_A + sw128(off + 64), Al + go);
        }
        for (int u = tid; u < BN * 4; u += 256) {
            int r = u >> 2;
            int kb = u & 3;
            long long go = (long long)(n0 + r) * ldb + kt + kb * 8;
            uint32_t off = ((uint32_t)r << 7) | ((uint32_t)kb << 4);
            cpa16(base + S_B + sw128(off), Bh + go);
            cpa16(base + S_B + sw128(off + 64), Bl + go);
        }
    };

    float acc[MF][NF][4];
    #pragma unroll
    for (int a = 0; a < MF; a++)
        #pragma unroll
        for (int b = 0; b < NF; b++)
            #pragma unroll
            for (int c = 0; c < 4; c++)
                acc[a][b][c] = 0.f;

    stage_chunk(0, kbeg);
    CP_COMMIT();

    for (int t = 0; t < nch; t++) {
        if (t + 1 < nch) {
            stage_chunk((t + 1) & 1, kbeg + (t + 1) * 32);
            CP_COMMIT();
            CP_WAIT1();
        } else {
            CP_WAIT0();
        }
        __syncthreads();

        uint32_t cbase = sb + (t & 1) * STG;
        #pragma unroll
        for (int ks = 0; ks < 2; ks++) {
            int g = lane >> 3;
            int rowin = lane & 7;
            // A fragments: x4 per mf (16m x 16k), hi and lo
            int kbA = ks * 32 + (g >> 1) * 16;
            uint32_t ahf[MF][4], alf[MF][4];
            #pragma unroll
            for (int mf = 0; mf < MF; mf++) {
                int r = wm * WM + mf * 16 + (g & 1) * 8 + rowin;
                uint32_t off = ((uint32_t)r << 7) + (uint32_t)kbA;
                ldm4(ahf[mf], cbase + S_A + sw128(off));
                ldm4(alf[mf], cbase + S_A + sw128(off + 64));
            }
            // B fragments: x4 loads a PAIR of n8 tiles (nf, nf+1)
            int kbB = ks * 32 + ((lane >> 3) & 1) * 16;
            int rowB = ((lane >> 4) & 1) * 8 + rowin;
            uint32_t bhf[NF][2], blf[NF][2];
            #pragma unroll
            for (int nfp = 0; nfp < NF; nfp += 2) {
                int r = wn * WN + nfp * 8 + rowB;
                uint32_t off = ((uint32_t)r << 7) + (uint32_t)kbB;
                uint32_t q[4];
                ldm4(q, cbase + S_B + sw128(off));
                bhf[nfp][0] = q[0]; bhf[nfp][1] = q[1];
                bhf[nfp + 1][0] = q[2]; bhf[nfp + 1][1] = q[3];
                ldm4(q, cbase + S_B + sw128(off + 64));
                blf[nfp][0] = q[0]; blf[nfp][1] = q[1];
                blf[nfp + 1][0] = q[2]; blf[nfp + 1][1] = q[3];
            }
            #pragma unroll
            for (int mf = 0; mf < MF; mf++) {
                #pragma unroll
                for (int nf = 0; nf < NF; nf++) {
                    mma16816(acc[mf][nf], ahf[mf], bhf[nf]);
                    mma16816(acc[mf][nf], ahf[mf], blf[nf]);
                    mma16816(acc[mf][nf], alf[mf], bhf[nf]);
                }
            }
        }
        __syncthreads();
    }

    // epilogue from register fragments (vectorized 2-column stores)
    int crow = lane >> 2;
    int ccol = (lane & 3) * 2;
    #pragma unroll
    for (int mf = 0; mf < MF; mf++) {
        #pragma unroll
        for (int nf = 0; nf < NF; nf++) {
            #pragma unroll
            for (int c2 = 0; c2 < 2; c2++) {
                int gi = i0 + wm * WM + mf * 16 + crow + c2 * 8;
                int gj = n0 + wn * WN + nf * 8 + ccol;
                float v0 = acc[mf][nf][c2 * 2];
                float v1 = acc[mf][nf][c2 * 2 + 1];
                long long idx = (long long)gi * ldc + gj;
                if (epi == 0) {
                    float2 f2;
                    f2.x = v0;
                    f2.y = v1;
                    *(float2*)(Cf + idx) = f2;
                } else {
                    if (epi == 1) {
                        int c0 = gj >> 10;
                        int c1 = (gj + 1) >> 10;
                        if (c0 == 0 || c0 == 3) v0 *= 0.125f;
                        if (c1 == 0 || c1 == 3) v1 *= 0.125f;
                    } else if (epi == 2) {
                        v0 = (gj <= gi) ? v0 : 0.f;
                        v1 = (gj + 1 <= gi) ? v1 : 0.f;
                    } else if (epi == 3) {
                        v0 = (gj > gi) ? (1.f / (1.f + expf(-v0))) : 0.f;
                        v1 = (gj + 1 > gi) ? (1.f / (1.f + expf(-v1))) : 0.f;
                    }
                    bf16 h0 = f2bf(v0);
                    bf16 h1 = f2bf(v1);
                    uint32_t hp = (uint32_t)h0 | ((uint32_t)h1 << 16);
                    uint32_t lp = (uint32_t)f2bf(v0 - bf2f(h0)) | ((uint32_t)f2bf(v1 - bf2f(h1)) << 16);
                    *(uint32_t*)(Ch + idx) = hp;
                    *(uint32_t*)(Cl + idx) = lp;
                }
            }
        }
    }
}

// ---------------- split fp32 -> (hi, lo) bf16 ----------------
__global__ void split_kernel(const float* __restrict__ s, bf16* __restrict__ h,
                             bf16* __restrict__ l, int n4)
{
    int i = blockIdx.x * 256 + threadIdx.x;
    if (i < n4) {
        float4 v = ((const float4*)s)[i];
        float vv[4];
        vv[0] = v.x; vv[1] = v.y; vv[2] = v.z; vv[3] = v.w;
        for (int k = 0; k < 4; k++) {
            bf16 hh = f2bf(vv[k]);
            h[i * 4 + k] = hh;
            l[i * 4 + k] = f2bf(vv[k] - bf2f(hh));
        }
    }
}

// ---------------- transpose vc: [n][5120 + c] -> [c][n] ----------------
__global__ void transpose_vc(const bf16* __restrict__ qh, const bf16* __restrict__ ql,
                             bf16* __restrict__ vth, bf16* __restrict__ vtl)
{
    __shared__ bf16 th[32][33];
    __shared__ bf16 tl[32][33];
    int c0 = blockIdx.x * 32;
    int n0 = blockIdx.y * 32;
    int tx = threadIdx.x;
    int ty = threadIdx.y;
    for (int r = ty; r < 32; r += 8) {
        th[r][tx] = qh[(long long)(n0 + r) * QKV6 + 5120 + c0 + tx];
        tl[r][tx] = ql[(long long)(n0 + r) * QKV6 + 5120 + c0 + tx];
    }
    __syncthreads();
    for (int r = ty; r < 32; r += 8) {
        vth[(long long)(c0 + r) * NSEQ + n0 + tx] = th[tx][r];
        vtl[(long long)(c0 + r) * NSEQ + n0 + tx] = tl[tx][r];
    }
}

// ---------------- softmax(Sc - silu(Su)) over j<=i -> attn bf16 pair ----------------
__global__ void softmax_kernel(const float* __restrict__ sc, const float* __restrict__ su,
                               bf16* __restrict__ ah, bf16* __restrict__ al, int n)
{
    int i = blockIdx.x;
    int hh = blockIdx.y;
    long long base = ((long long)hh * n + i) * (long long)n;
    const float* scr = sc + base;
    const float* sur = su + base;
    bf16* ahr = ah + base;
    bf16* alr = al + base;

    int tid = threadIdx.x;
    const int NT = 256;
    float vals[8];
    int cnt = 0;
    float lmax = -INFINITY;
    for (int j = tid; j <= i; j += NT) {
        float u = sur[j];
        float sg = 1.f / (1.f + expf(-u));
        float s = scr[j] - u * sg;
        vals[cnt] = s;
        cnt++;
        lmax = fmaxf(lmax, s);
    }

    __shared__ float red[33];
    for (int o = 16; o > 0; o >>= 1) lmax = fmaxf(lmax, __shfl_xor_sync(0xffffffffu, lmax, o));
    if ((tid & 31) == 0) red[tid >> 5] = lmax;
    __syncthreads();
    if (tid == 0) {
        float m0 = red[0];
        for (int w = 1; w < NT / 32; w++) m0 = fmaxf(m0, red[w]);
        red[32] = m0;
    }
    __syncthreads();
    float m = red[32];
    __syncthreads();

    float lsum = 0.f;
    for (int c = 0; c < cnt; c++) {
        float e = expf(vals[c] - m);
        vals[c] = e;
        lsum += e;
    }
    for (int o = 16; o > 0; o >>= 1) lsum += __shfl_xor_sync(0xffffffffu, lsum, o);
    if ((tid & 31) == 0) red[tid >> 5] = lsum;
    __syncthreads();
    if (tid == 0) {
        float s0 = 0.f;
        for (int w = 0; w < NT / 32; w++) s0 += red[w];
        red[32] = s0;
    }
    __syncthreads();
    float inv = 1.f / red[32];

    cnt = 0;
    for (int j = tid; j <= i; j += NT) {
        float v = vals[cnt] * inv;
        cnt++;
        bf16 vh = f2bf(v);
        ahr[j] = vh;
        alr[j] = f2bf(v - bf2f(vh));
    }
    int jend = (((i >> 7) + 1) << 7);
    for (int j = i + 1 + tid; j < jend; j += NT) {
        ahr[j] = 0;
        alr[j] = 0;
    }
}

extern "C" void kernel_launch(void* const* d_in, const int* in_sizes, int n_in,
                              void* d_out, int out_size)
{
    const float* x     = (const float*)d_in[0];
    const float* w_qkv = (const float*)d_in[1];
    const float* w_out = (const float*)d_in[2];
    float* out = (float*)d_out;

    bf16 *xh, *xl, *wqh, *wql, *woh, *wol, *qh, *ql, *vth, *vtl;
    bf16 *t1h, *t1l, *sgh, *sgl, *ah, *al, *oh, *ol;
    float *sc, *su;
    cudaGetSymbolAddress((void**)&xh, g_xh);
    cudaGetSymbolAddress((void**)&xl, g_xl);
    cudaGetSymbolAddress((void**)&wqh, g_wqh);
    cudaGetSymbolAddress((void**)&wql, g_wql);
    cudaGetSymbolAddress((void**)&woh, g_woh);
    cudaGetSymbolAddress((void**)&wol, g_wol);
    cudaGetSymbolAddress((void**)&qh, g_qh);
    cudaGetSymbolAddress((void**)&ql, g_ql);
    cudaGetSymbolAddress((void**)&vth, g_vth);
    cudaGetSymbolAddress((void**)&vtl, g_vtl);
    cudaGetSymbolAddress((void**)&t1h, g_t1h);
    cudaGetSymbolAddress((void**)&t1l, g_t1l);
    cudaGetSymbolAddress((void**)&sgh, g_sgh);
    cudaGetSymbolAddress((void**)&sgl, g_sgl);
    cudaGetSymbolAddress((void**)&sc, g_sc);
    cudaGetSymbolAddress((void**)&su, g_su);
    cudaGetSymbolAddress((void**)&ah, g_ah);
    cudaGetSymbolAddress((void**)&al, g_al);
    cudaGetSymbolAddress((void**)&oh, g_oh);
    cudaGetSymbolAddress((void**)&ol, g_ol);

    const int SMT128 = 2 * (16384 + 128 * 128);  // 65536
    const int SMT64  = 2 * (16384 + 64 * 128);   // 49152
    cudaFuncSetAttribute(mma_gemm<128, 2>, cudaFuncAttributeMaxDynamicSharedMemorySize, SMT128);
    cudaFuncSetAttribute(mma_gemm<64, 4>, cudaFuncAttributeMaxDynamicSharedMemorySize, SMT64);

    // splits
    {
        int n4 = NSEQ * DIM / 4;
        split_kernel<<<(n4 + 255) / 256, 256>>>(x, xh, xl, n4);
        n4 = QKV6 * DIM / 4;
        split_kernel<<<(n4 + 255) / 256, 256>>>(w_qkv, wqh, wql, n4);
        n4 = DIM * DIM / 4;
        split_kernel<<<(n4 + 255) / 256, 256>>>(w_out, woh, wol, n4);
    }

    // 1) qkvs = x @ w_qkv^T (scale qu,qc by 0.125), split pair
    mma_gemm<128, 2><<<dim3(QKV6 / 128, NSEQ / 128, 1), 256, SMT128>>>(
        xh, xl, DIM, 0, wqh, wql, DIM, 0,
        (float*)0, qh, ql, (bf16*)0, (bf16*)0, QKV6, 0,
        DIM, 1, 0, 0, 0);

    // 1b) transpose vc -> [64][N] per head
    transpose_vc<<<dim3(DIM / 32, NSEQ / 32), dim3(32, 8)>>>(qh, ql, vth, vtl);

    // 2-4 fused) comp0: term1 = qc@vu^T (epi2); comp1: sig = sigmoid(qu@ku^T) (epi3);
    //            comp2: Sc = qc@kc^T (epi0). z = h*3+comp.
    mma_gemm<128, 2><<<dim3(16, 16, HEADS * 3), 256, SMT128>>>(
        qh, ql, QKV6, 0, qh, ql, QKV6, 0,
        sc, t1h, t1l, sgh, sgl, NSEQ, 0,
        64, 0, 0, 0, /*fuse3*/1);

    // 5) Su = term1 @ sig^T, triangular k-range, fp32
    mma_gemm<128, 2><<<dim3(16, 16, HEADS), 256, SMT128>>>(
        t1h, t1l, NSEQ, HSLL, sgh, sgl, NSEQ, HSLL,
        su, (bf16*)0, (bf16*)0, (bf16*)0, (bf16*)0, NSEQ, HSLL,
        NSEQ, 0, 1, 1, 0);

    // 6) softmax(Sc - silu(Su)) -> attn split pair
    softmax_kernel<<<dim3(NSEQ, HEADS), 256>>>(sc, su, ah, al, NSEQ);

    // 7) o[:, h*64:(h+1)*64] = attn_h @ vcT_h (causal k-range)
    mma_gemm<64, 4><<<dim3(1, 16, HEADS), 256, SMT64>>>(
        ah, al, NSEQ, HSLL, vth, vtl, NSEQ, 64LL * NSEQ,
        (float*)0, oh, ol, (bf16*)0, (bf16*)0, HEADS * 64, 64,
        NSEQ, 4, 0, 2, 0);

    // 8) out = o @ w_out^T, fp32
    mma_gemm<128, 2><<<dim3(DIM / 128, NSEQ / 128, 1), 256, SMT128>>>(
        oh, ol, HEADS * 64, 0, woh, wol, HEADS * 64, 0,
        out, (bf16*)0, (bf16*)0, (bf16*)0, (bf16*)0, DIM, 0,
        HEADS * 64, 0, 0, 0, 0);
}

// round 13
// speedup vs baseline: 1.1757x; 1.0411x over previous
#include <cuda_runtime.h>
#include <math.h>
#include <stdint.h>

#define NSEQ 2048
#define DIM  1024
#define HEADS 16
#define QKV6 6144
#define HSLL ((long long)NSEQ * NSEQ)

typedef unsigned short bf16;

// ---------------- device scratch (allocation-free) ----------------
__device__ bf16 g_xh[NSEQ * DIM];
__device__ bf16 g_xl[NSEQ * DIM];
__device__ bf16 g_wqh[QKV6 * DIM];
__device__ bf16 g_wql[QKV6 * DIM];
__device__ bf16 g_woh[DIM * DIM];
__device__ bf16 g_wol[DIM * DIM];
__device__ bf16 g_qh[NSEQ * QKV6];
__device__ bf16 g_ql[NSEQ * QKV6];
__device__ bf16 g_vth[DIM * NSEQ];   // vc transposed: [h*64+d][n]
__device__ bf16 g_vtl[DIM * NSEQ];
__device__ bf16 g_t1h[(size_t)HEADS * NSEQ * NSEQ];
__device__ bf16 g_t1l[(size_t)HEADS * NSEQ * NSEQ];
__device__ bf16 g_sgh[(size_t)HEADS * NSEQ * NSEQ];
__device__ bf16 g_sgl[(size_t)HEADS * NSEQ * NSEQ];
__device__ float g_sc[(size_t)HEADS * NSEQ * NSEQ];
__device__ float g_su[(size_t)HEADS * NSEQ * NSEQ];
__device__ bf16 g_ah[(size_t)HEADS * NSEQ * NSEQ];
__device__ bf16 g_al[(size_t)HEADS * NSEQ * NSEQ];
__device__ bf16 g_oh[NSEQ * DIM];
__device__ bf16 g_ol[NSEQ * DIM];

// ---------------- helpers ----------------
__device__ __forceinline__ bf16 f2bf(float f) {
    bf16 h;
    asm("cvt.rn.bf16.f32 %0, %1;" : "=h"(h) : "f"(f));
    return h;
}
__device__ __forceinline__ float bf2f(bf16 h) {
    return __uint_as_float(((unsigned int)h) << 16);
}

__device__ __forceinline__ uint32_t smem_u32(const void* p) {
    uint32_t a;
    asm("{ .reg .u64 t; cvta.to.shared.u64 t, %1; cvt.u32.u64 %0, t; }" : "=r"(a) : "l"(p));
    return a;
}

__device__ __forceinline__ void cpa16(uint32_t saddr, const void* g) {
    asm volatile("cp.async.cg.shared.global [%0], [%1], 16;" :: "r"(saddr), "l"(g));
}
#define CP_COMMIT() asm volatile("cp.async.commit_group;" ::: "memory")
#define CP_WAIT0() asm volatile("cp.async.wait_group 0;" ::: "memory")
#define CP_WAIT1() asm volatile("cp.async.wait_group 1;" ::: "memory")

__device__ __forceinline__ void ldm4(uint32_t* r, uint32_t addr) {
    asm volatile("ldmatrix.sync.aligned.m8n8.x4.shared.b16 {%0,%1,%2,%3}, [%4];"
        : "=r"(r[0]), "=r"(r[1]), "=r"(r[2]), "=r"(r[3]) : "r"(addr));
}

__device__ __forceinline__ void mma16816(float* d, const uint32_t* a, const uint32_t* b) {
    asm volatile(
        "mma.sync.aligned.m16n8k16.row.col.f32.bf16.bf16.f32 "
        "{%0,%1,%2,%3}, {%4,%5,%6,%7}, {%8,%9}, {%0,%1,%2,%3};"
        : "+f"(d[0]), "+f"(d[1]), "+f"(d[2]), "+f"(d[3])
        : "r"(a[0]), "r"(a[1]), "r"(a[2]), "r"(a[3]), "r"(b[0]), "r"(b[1]));
}

// SW128 swizzle for 128-byte rows: XOR bits[6:4] with row bits[2:0]
__device__ __forceinline__ uint32_t sw128(uint32_t off) {
    return off ^ ((off >> 3) & 0x70);
}

// ---------------- warp-MMA GEMM engine ----------------
// bf16x3 split; rows are 128B: [32 bf16 hi | 32 bf16 lo]; SW128.
// cp.async 2-stage (R7 ordering), BK=32. B fragments loaded pairwise via ldmatrix.x4.
// C[i0+m][n0+n] = sum_k A[m][k]*B[n][k]
// epi: 0 fp32; 1 qkv-scale + split; 2 mask j<=i + split; 3 sigmoid strict-upper + split;
//      4 split; 6 fp32 = silu(acc).
// skipm: 1 skip n0>i0; 2 skip n0<i0. trik: 1 -> k in [n0, i0+128); 2 -> k in [0, i0+128).
// fuse3: z = h*3+comp; comp0=term1 (A qc, B vu, epi2), comp1=sig (A qu, B ku, epi3),
//        comp2=Sc (A qc, B kc, epi0). Ah/Bh bases are qh; outputs Ch/Cl=t1, Ch2/Cl2=sg, Cf=sc.
template<int BN, int WMC>
__global__ void __launch_bounds__(256, 2) mma_gemm(
    const bf16* __restrict__ Ah, const bf16* __restrict__ Al, int lda, long long sA,
    const bf16* __restrict__ Bh, const bf16* __restrict__ Bl, int ldb, long long sB,
    float* Cf, bf16* Ch, bf16* Cl, bf16* Ch2, bf16* Cl2, int ldc, long long sC,
    int K, int epi, int skipm, int trik, int fuse3)
{
    constexpr int WNC = 8 / WMC;
    constexpr int WM = 128 / WMC;
    constexpr int WN = BN / WNC;
    constexpr int MF = WM / 16;
    constexpr int NF = WN / 8;
    // stage layout: A 128 rows x 128B = 16KB, B BN rows x 128B
    constexpr int S_A = 0;
    constexpr int S_B = 16384;
    constexpr int STG = 16384 + BN * 128;

    int i0 = blockIdx.y * 128;
    int n0 = blockIdx.x * BN;
    int z = blockIdx.z;

    if (fuse3) {
        int comp = z % 3;
        int h = z / 3;
        skipm = (comp == 1) ? 2 : 1;
        epi = (comp == 0) ? 2 : ((comp == 1) ? 3 : 0);
        if (skipm == 1 && n0 > i0) return;
        if (skipm == 2 && n0 < i0) return;
        int aoff = (comp == 1) ? 0 : 3072;
        int boff = (comp == 0) ? 2048 : ((comp == 1) ? 1024 : 4096);
        Ah += h * 64 + aoff;
        Al += h * 64 + aoff;
        Bh += h * 64 + boff;
        Bl += h * 64 + boff;
        long long hs = (long long)h * HSLL;
        if (comp == 2) {
            Cf += hs;
        } else if (comp == 0) {
            Ch += hs;
            Cl += hs;
        } else {
            Ch = Ch2 + hs;
            Cl = Cl2 + hs;
        }
    } else {
        if (skipm == 1 && n0 > i0) return;
        if (skipm == 2 && n0 < i0) return;
        Ah += (long long)z * sA;
        Al += (long long)z * sA;
        Bh += (long long)z * sB;
        Bl += (long long)z * sB;
        if (Cf) Cf += (long long)z * sC;
        if (Ch) {
            Ch += (long long)z * sC;
            Cl += (long long)z * sC;
        }
    }

    int kbeg = 0;
    int kend = K;
    if (trik == 1) {
        kbeg = n0;
        kend = i0 + 128;
        if (kend > K) kend = K;
    } else if (trik == 2) {
        kend = i0 + 128;
        if (kend > K) kend = K;
    }
    int nch = (kend - kbeg + 31) >> 5;

    extern __shared__ __align__(1024) char smem[];
    uint32_t sb = smem_u32(smem);
    int tid = threadIdx.x;
    int wid = tid >> 5;
    int lane = tid & 31;
    int wm = wid % WMC;
    int wn = wid / WMC;

    auto stage_chunk = [&](int buf, int kt) {
        uint32_t base = sb + buf * STG;
        for (int u = tid; u < 512; u += 256) {
            int r = u >> 2;
            int kb = u & 3;
            long long go = (long long)(i0 + r) * lda + kt + kb * 8;
            uint32_t off = ((uint32_t)r << 7) | ((uint32_t)kb << 4);
            cpa16(base + S_A + sw128(off), Ah + go);
            cpa16(base + S_A + sw128(off + 64), Al + go);
        }
        for (int u = tid; u < BN * 4; u += 256) {
            int r = u >> 2;
            int kb = u & 3;
            long long go = (long long)(n0 + r) * ldb + kt + kb * 8;
            uint32_t off = ((uint32_t)r << 7) | ((uint32_t)kb << 4);
            cpa16(base + S_B + sw128(off), Bh + go);
            cpa16(base + S_B + sw128(off + 64), Bl + go);
        }
    };

    float acc[MF][NF][4];
    #pragma unroll
    for (int a = 0; a < MF; a++)
        #pragma unroll
        for (int b = 0; b < NF; b++)
            #pragma unroll
            for (int c = 0; c < 4; c++)
                acc[a][b][c] = 0.f;

    stage_chunk(0, kbeg);
    CP_COMMIT();

    for (int t = 0; t < nch; t++) {
        if (t + 1 < nch) {
            stage_chunk((t + 1) & 1, kbeg + (t + 1) * 32);
            CP_COMMIT();
            CP_WAIT1();
        } else {
            CP_WAIT0();
        }
        __syncthreads();

        uint32_t cbase = sb + (t & 1) * STG;
        #pragma unroll
        for (int ks = 0; ks < 2; ks++) {
            int g = lane >> 3;
            int rowin = lane & 7;
            // A fragments: x4 per mf (16m x 16k), hi and lo
            int kbA = ks * 32 + (g >> 1) * 16;
            uint32_t ahf[MF][4], alf[MF][4];
            #pragma unroll
            for (int mf = 0; mf < MF; mf++) {
                int r = wm * WM + mf * 16 + (g & 1) * 8 + rowin;
                uint32_t off = ((uint32_t)r << 7) + (uint32_t)kbA;
                ldm4(ahf[mf], cbase + S_A + sw128(off));
                ldm4(alf[mf], cbase + S_A + sw128(off + 64));
            }
            // B fragments: x4 loads a PAIR of n8 tiles (nf, nf+1)
            int kbB = ks * 32 + ((lane >> 3) & 1) * 16;
            int rowB = ((lane >> 4) & 1) * 8 + rowin;
            uint32_t bhf[NF][2], blf[NF][2];
            #pragma unroll
            for (int nfp = 0; nfp < NF; nfp += 2) {
                int r = wn * WN + nfp * 8 + rowB;
                uint32_t off = ((uint32_t)r << 7) + (uint32_t)kbB;
                uint32_t q[4];
                ldm4(q, cbase + S_B + sw128(off));
                bhf[nfp][0] = q[0]; bhf[nfp][1] = q[1];
                bhf[nfp + 1][0] = q[2]; bhf[nfp + 1][1] = q[3];
                ldm4(q, cbase + S_B + sw128(off + 64));
                blf[nfp][0] = q[0]; blf[nfp][1] = q[1];
                blf[nfp + 1][0] = q[2]; blf[nfp + 1][1] = q[3];
            }
            #pragma unroll
            for (int mf = 0; mf < MF; mf++) {
                #pragma unroll
                for (int nf = 0; nf < NF; nf++) {
                    mma16816(acc[mf][nf], ahf[mf], bhf[nf]);
                    mma16816(acc[mf][nf], ahf[mf], blf[nf]);
                    mma16816(acc[mf][nf], alf[mf], bhf[nf]);
                }
            }
        }
        __syncthreads();
    }

    // epilogue from register fragments (vectorized 2-column stores)
    int crow = lane >> 2;
    int ccol = (lane & 3) * 2;
    #pragma unroll
    for (int mf = 0; mf < MF; mf++) {
        #pragma unroll
        for (int nf = 0; nf < NF; nf++) {
            #pragma unroll
            for (int c2 = 0; c2 < 2; c2++) {
                int gi = i0 + wm * WM + mf * 16 + crow + c2 * 8;
                int gj = n0 + wn * WN + nf * 8 + ccol;
                float v0 = acc[mf][nf][c2 * 2];
                float v1 = acc[mf][nf][c2 * 2 + 1];
                long long idx = (long long)gi * ldc + gj;
                if (epi == 0) {
                    float2 f2;
                    f2.x = v0;
                    f2.y = v1;
                    *(float2*)(Cf + idx) = f2;
                } else if (epi == 6) {
                    float2 f2;
                    f2.x = v0 / (1.f + expf(-v0));
                    f2.y = v1 / (1.f + expf(-v1));
                    *(float2*)(Cf + idx) = f2;
                } else {
                    if (epi == 1) {
                        int c0 = gj >> 10;
                        int c1 = (gj + 1) >> 10;
                        if (c0 == 0 || c0 == 3) v0 *= 0.125f;
                        if (c1 == 0 || c1 == 3) v1 *= 0.125f;
                    } else if (epi == 2) {
                        v0 = (gj <= gi) ? v0 : 0.f;
                        v1 = (gj + 1 <= gi) ? v1 : 0.f;
                    } else if (epi == 3) {
                        v0 = (gj > gi) ? (1.f / (1.f + expf(-v0))) : 0.f;
                        v1 = (gj + 1 > gi) ? (1.f / (1.f + expf(-v1))) : 0.f;
                    }
                    bf16 h0 = f2bf(v0);
                    bf16 h1 = f2bf(v1);
                    uint32_t hp = (uint32_t)h0 | ((uint32_t)h1 << 16);
                    uint32_t lp = (uint32_t)f2bf(v0 - bf2f(h0)) | ((uint32_t)f2bf(v1 - bf2f(h1)) << 16);
                    *(uint32_t*)(Ch + idx) = hp;
                    *(uint32_t*)(Cl + idx) = lp;
                }
            }
        }
    }
}

// ---------------- split fp32 -> (hi, lo) bf16 ----------------
__global__ void split_kernel(const float* __restrict__ s, bf16* __restrict__ h,
                             bf16* __restrict__ l, int n4)
{
    int i = blockIdx.x * 256 + threadIdx.x;
    if (i < n4) {
        float4 v = ((const float4*)s)[i];
        float vv[4];
        vv[0] = v.x; vv[1] = v.y; vv[2] = v.z; vv[3] = v.w;
        for (int k = 0; k < 4; k++) {
            bf16 hh = f2bf(vv[k]);
            h[i * 4 + k] = hh;
            l[i * 4 + k] = f2bf(vv[k] - bf2f(hh));
        }
    }
}

// ---------------- transpose vc: [n][5120 + c] -> [c][n] ----------------
__global__ void transpose_vc(const bf16* __restrict__ qh, const bf16* __restrict__ ql,
                             bf16* __restrict__ vth, bf16* __restrict__ vtl)
{
    __shared__ bf16 th[32][33];
    __shared__ bf16 tl[32][33];
    int c0 = blockIdx.x * 32;
    int n0 = blockIdx.y * 32;
    int tx = threadIdx.x;
    int ty = threadIdx.y;
    for (int r = ty; r < 32; r += 8) {
        th[r][tx] = qh[(long long)(n0 + r) * QKV6 + 5120 + c0 + tx];
        tl[r][tx] = ql[(long long)(n0 + r) * QKV6 + 5120 + c0 + tx];
    }
    __syncthreads();
    for (int r = ty; r < 32; r += 8) {
        vth[(long long)(c0 + r) * NSEQ + n0 + tx] = th[tx][r];
        vtl[(long long)(c0 + r) * NSEQ + n0 + tx] = tl[tx][r];
    }
}

// ---------------- softmax(sc - su_presilu) over j<=i -> attn bf16 pair, vectorized ----------------
__global__ void softmax_kernel(const float* __restrict__ sc, const float* __restrict__ su,
                               bf16* __restrict__ ah, bf16* __restrict__ al, int n)
{
    int i = blockIdx.x;
    int hh = blockIdx.y;
    long long base = ((long long)hh * n + i) * (long long)n;
    const float* scr = sc + base;
    const float* sur = su + base;
    bf16* ahr = ah + base;
    bf16* alr = al + base;

    int tid = threadIdx.x;
    const int NT = 256;
    float vals[8];
    int np = 0;
    float lmax = -INFINITY;
    for (int j = tid * 4; j <= i; j += NT * 4) {
        float4 s4 = *(const float4*)(scr + j);
        float4 u4 = *(const float4*)(sur + j);
        float v[4];
        v[0] = s4.x - u4.x;
        v[1] = s4.y - u4.y;
        v[2] = s4.z - u4.z;
        v[3] = s4.w - u4.w;
        #pragma unroll
        for (int e = 0; e < 4; e++) {
            if (j + e > i) v[e] = -INFINITY;
            vals[np * 4 + e] = v[e];
            lmax = fmaxf(lmax, v[e]);
        }
        np++;
    }

    __shared__ float red[33];
    for (int o = 16; o > 0; o >>= 1) lmax = fmaxf(lmax, __shfl_xor_sync(0xffffffffu, lmax, o));
    if ((tid & 31) == 0) red[tid >> 5] = lmax;
    __syncthreads();
    if (tid == 0) {
        float m0 = red[0];
        for (int w = 1; w < NT / 32; w++) m0 = fmaxf(m0, red[w]);
        red[32] = m0;
    }
    __syncthreads();
    float m = red[32];
    __syncthreads();

    float lsum = 0.f;
    for (int p = 0; p < np; p++) {
        #pragma unroll
        for (int e = 0; e < 4; e++) {
            float ex = expf(vals[p * 4 + e] - m);
            vals[p * 4 + e] = ex;
            lsum += ex;
        }
    }
    for (int o = 16; o > 0; o >>= 1) lsum += __shfl_xor_sync(0xffffffffu, lsum, o);
    if ((tid & 31) == 0) red[tid >> 5] = lsum;
    __syncthreads();
    if (tid == 0) {
        float s0 = 0.f;
        for (int w = 0; w < NT / 32; w++) s0 += red[w];
        red[32] = s0;
    }
    __syncthreads();
    float inv = 1.f / red[32];

    int p = 0;
    for (int j = tid * 4; j <= i; j += NT * 4, p++) {
        float v0 = vals[p * 4 + 0] * inv;
        float v1 = vals[p * 4 + 1] * inv;
        float v2 = vals[p * 4 + 2] * inv;
        float v3 = vals[p * 4 + 3] * inv;
        bf16 h0 = f2bf(v0), h1 = f2bf(v1), h2 = f2bf(v2), h3 = f2bf(v3);
        uint2 hp, lp;
        hp.x = (uint32_t)h0 | ((uint32_t)h1 << 16);
        hp.y = (uint32_t)h2 | ((uint32_t)h3 << 16);
        lp.x = (uint32_t)f2bf(v0 - bf2f(h0)) | ((uint32_t)f2bf(v1 - bf2f(h1)) << 16);
        lp.y = (uint32_t)f2bf(v2 - bf2f(h2)) | ((uint32_t)f2bf(v3 - bf2f(h3)) << 16);
        *(uint2*)(ahr + j) = hp;
        *(uint2*)(alr + j) = lp;
    }
    // zero-fill from next 4-pack through the 128-tile boundary
    int jz = ((i >> 2) + 1) << 2;
    int jend = (((i >> 7) + 1) << 7);
    uint2 zz;
    zz.x = 0;
    zz.y = 0;
    for (int j = jz + tid * 4; j < jend; j += NT * 4) {
        *(uint2*)(ahr + j) = zz;
        *(uint2*)(alr + j) = zz;
    }
}

extern "C" void kernel_launch(void* const* d_in, const int* in_sizes, int n_in,
                              void* d_out, int out_size)
{
    const float* x     = (const float*)d_in[0];
    const float* w_qkv = (const float*)d_in[1];
    const float* w_out = (const float*)d_in[2];
    float* out = (float*)d_out;

    bf16 *xh, *xl, *wqh, *wql, *woh, *wol, *qh, *ql, *vth, *vtl;
    bf16 *t1h, *t1l, *sgh, *sgl, *ah, *al, *oh, *ol;
    float *sc, *su;
    cudaGetSymbolAddress((void**)&xh, g_xh);
    cudaGetSymbolAddress((void**)&xl, g_xl);
    cudaGetSymbolAddress((void**)&wqh, g_wqh);
    cudaGetSymbolAddress((void**)&wql, g_wql);
    cudaGetSymbolAddress((void**)&woh, g_woh);
    cudaGetSymbolAddress((void**)&wol, g_wol);
    cudaGetSymbolAddress((void**)&qh, g_qh);
    cudaGetSymbolAddress((void**)&ql, g_ql);
    cudaGetSymbolAddress((void**)&vth, g_vth);
    cudaGetSymbolAddress((void**)&vtl, g_vtl);
    cudaGetSymbolAddress((void**)&t1h, g_t1h);
    cudaGetSymbolAddress((void**)&t1l, g_t1l);
    cudaGetSymbolAddress((void**)&sgh, g_sgh);
    cudaGetSymbolAddress((void**)&sgl, g_sgl);
    cudaGetSymbolAddress((void**)&sc, g_sc);
    cudaGetSymbolAddress((void**)&su, g_su);
    cudaGetSymbolAddress((void**)&ah, g_ah);
    cudaGetSymbolAddress((void**)&al, g_al);
    cudaGetSymbolAddress((void**)&oh, g_oh);
    cudaGetSymbolAddress((void**)&ol, g_ol);

    const int SMT128 = 2 * (16384 + 128 * 128);  // 65536
    const int SMT64  = 2 * (16384 + 64 * 128);   // 49152
    cudaFuncSetAttribute(mma_gemm<128, 2>, cudaFuncAttributeMaxDynamicSharedMemorySize, SMT128);
    cudaFuncSetAttribute(mma_gemm<64, 4>, cudaFuncAttributeMaxDynamicSharedMemorySize, SMT64);

    // splits
    {
        int n4 = NSEQ * DIM / 4;
        split_kernel<<<(n4 + 255) / 256, 256>>>(x, xh, xl, n4);
        n4 = QKV6 * DIM / 4;
        split_kernel<<<(n4 + 255) / 256, 256>>>(w_qkv, wqh, wql, n4);
        n4 = DIM * DIM / 4;
        split_kernel<<<(n4 + 255) / 256, 256>>>(w_out, woh, wol, n4);
    }

    // 1) qkvs = x @ w_qkv^T (scale qu,qc by 0.125), split pair
    mma_gemm<128, 2><<<dim3(QKV6 / 128, NSEQ / 128, 1), 256, SMT128>>>(
        xh, xl, DIM, 0, wqh, wql, DIM, 0,
        (float*)0, qh, ql, (bf16*)0, (bf16*)0, QKV6, 0,
        DIM, 1, 0, 0, 0);

    // 1b) transpose vc -> [64][N] per head
    transpose_vc<<<dim3(DIM / 32, NSEQ / 32), dim3(32, 8)>>>(qh, ql, vth, vtl);

    // 2-4 fused) comp0: term1 = qc@vu^T (epi2); comp1: sig = sigmoid(qu@ku^T) (epi3);
    //            comp2: Sc = qc@kc^T (epi0). z = h*3+comp.
    mma_gemm<128, 2><<<dim3(16, 16, HEADS * 3), 256, SMT128>>>(
        qh, ql, QKV6, 0, qh, ql, QKV6, 0,
        sc, t1h, t1l, sgh, sgl, NSEQ, 0,
        64, 0, 0, 0, /*fuse3*/1);

    // 5) su = silu(term1 @ sig^T), triangular k-range (epi 6)
    mma_gemm<128, 2><<<dim3(16, 16, HEADS), 256, SMT128>>>(
        t1h, t1l, NSEQ, HSLL, sgh, sgl, NSEQ, HSLL,
        su, (bf16*)0, (bf16*)0, (bf16*)0, (bf16*)0, NSEQ, HSLL,
        NSEQ, 6, 1, 1, 0);

    // 6) softmax(sc - su) -> attn split pair (su already silu'd)
    softmax_kernel<<<dim3(NSEQ, HEADS), 256>>>(sc, su, ah, al, NSEQ);

    // 7) o[:, h*64:(h+1)*64] = attn_h @ vcT_h (causal k-range)
    mma_gemm<64, 4><<<dim3(1, 16, HEADS), 256, SMT64>>>(
        ah, al, NSEQ, HSLL, vth, vtl, NSEQ, 64LL * NSEQ,
        (float*)0, oh, ol, (bf16*)0, (bf16*)0, HEADS * 64, 64,
        NSEQ, 4, 0, 2, 0);

    // 8) out = o @ w_out^T, fp32
    mma_gemm<128, 2><<<dim3(DIM / 128, NSEQ / 128, 1), 256, SMT128>>>(
        oh, ol, HEADS * 64, 0, woh, wol, HEADS * 64, 0,
        out, (bf16*)0, (bf16*)0, (bf16*)0, (bf16*)0, DIM, 0,
        HEADS * 64, 0, 0, 0, 0);
}

// round 14
// speedup vs baseline: 1.2082x; 1.0276x over previous
#include <cuda_runtime.h>
#include <math.h>
#include <stdint.h>

#define NSEQ 2048
#define DIM  1024
#define HEADS 16
#define QKV6 6144
#define HSLL ((long long)NSEQ * NSEQ)

typedef unsigned short bf16;

// ---------------- device scratch (allocation-free) ----------------
__device__ bf16 g_xh[NSEQ * DIM];
__device__ bf16 g_xl[NSEQ * DIM];
__device__ bf16 g_wqh[QKV6 * DIM];
__device__ bf16 g_wql[QKV6 * DIM];
__device__ bf16 g_woh[DIM * DIM];
__device__ bf16 g_wol[DIM * DIM];
__device__ bf16 g_qh[NSEQ * QKV6];
__device__ bf16 g_ql[NSEQ * QKV6];
__device__ bf16 g_vth[DIM * NSEQ];   // vc transposed: [h*64+d][n]
__device__ bf16 g_vtl[DIM * NSEQ];
__device__ bf16 g_t1h[(size_t)HEADS * NSEQ * NSEQ];
__device__ bf16 g_t1l[(size_t)HEADS * NSEQ * NSEQ];
__device__ bf16 g_sgh[(size_t)HEADS * NSEQ * NSEQ];
__device__ bf16 g_sgl[(size_t)HEADS * NSEQ * NSEQ];
__device__ float g_sc[(size_t)HEADS * NSEQ * NSEQ];
__device__ float g_su[(size_t)HEADS * NSEQ * NSEQ];
__device__ bf16 g_ah[(size_t)HEADS * NSEQ * NSEQ];
__device__ bf16 g_al[(size_t)HEADS * NSEQ * NSEQ];
__device__ float g_op[4 * NSEQ * DIM];   // split-K partials for attn@vc
__device__ bf16 g_oh[NSEQ * DIM];
__device__ bf16 g_ol[NSEQ * DIM];

// ---------------- helpers ----------------
__device__ __forceinline__ bf16 f2bf(float f) {
    bf16 h;
    asm("cvt.rn.bf16.f32 %0, %1;" : "=h"(h) : "f"(f));
    return h;
}
__device__ __forceinline__ float bf2f(bf16 h) {
    return __uint_as_float(((unsigned int)h) << 16);
}

__device__ __forceinline__ uint32_t smem_u32(const void* p) {
    uint32_t a;
    asm("{ .reg .u64 t; cvta.to.shared.u64 t, %1; cvt.u32.u64 %0, t; }" : "=r"(a) : "l"(p));
    return a;
}

__device__ __forceinline__ void cpa16(uint32_t saddr, const void* g) {
    asm volatile("cp.async.cg.shared.global [%0], [%1], 16;" :: "r"(saddr), "l"(g));
}
#define CP_COMMIT() asm volatile("cp.async.commit_group;" ::: "memory")
#define CP_WAIT0() asm volatile("cp.async.wait_group 0;" ::: "memory")
#define CP_WAIT1() asm volatile("cp.async.wait_group 1;" ::: "memory")

__device__ __forceinline__ void ldm4(uint32_t* r, uint32_t addr) {
    asm volatile("ldmatrix.sync.aligned.m8n8.x4.shared.b16 {%0,%1,%2,%3}, [%4];"
        : "=r"(r[0]), "=r"(r[1]), "=r"(r[2]), "=r"(r[3]) : "r"(addr));
}

__device__ __forceinline__ void mma16816(float* d, const uint32_t* a, const uint32_t* b) {
    asm volatile(
        "mma.sync.aligned.m16n8k16.row.col.f32.bf16.bf16.f32 "
        "{%0,%1,%2,%3}, {%4,%5,%6,%7}, {%8,%9}, {%0,%1,%2,%3};"
        : "+f"(d[0]), "+f"(d[1]), "+f"(d[2]), "+f"(d[3])
        : "r"(a[0]), "r"(a[1]), "r"(a[2]), "r"(a[3]), "r"(b[0]), "r"(b[1]));
}

// SW128 swizzle for 128-byte rows: XOR bits[6:4] with row bits[2:0]
__device__ __forceinline__ uint32_t sw128(uint32_t off) {
    return off ^ ((off >> 3) & 0x70);
}

// ---------------- warp-MMA GEMM engine ----------------
// bf16x3 split; rows are 128B: [32 bf16 hi | 32 bf16 lo]; SW128.
// cp.async 2-stage (R7 ordering), BK=32. B fragments loaded pairwise via ldmatrix.x4.
// C[i0+m][n0+n] = sum_k A[m][k]*B[n][k]
// epi: 0 fp32; 1 qkv-scale + split; 2 mask j<=i + split; 3 sigmoid strict-upper + split;
//      4 split; 6 fp32 = silu(acc).
// skipm: 1 skip n0>i0; 2 skip n0<i0.
// trik: 1 -> k in [n0, i0+128); 2 -> k in [0, i0+128);
//       3 -> split-K: blockIdx.x = 512-wide k-segment of [0, i0+128), n0=0, Cf += seg*NSEQ*DIM.
// fuse3: z = h*3+comp; comp0=term1 (A qc, B vu, epi2), comp1=sig (A qu, B ku, epi3),
//        comp2=Sc (A qc, B kc, epi0). Ah/Bh bases are qh; outputs Ch/Cl=t1, Ch2/Cl2=sg, Cf=sc.
template<int BN, int WMC>
__global__ void __launch_bounds__(256, 2) mma_gemm(
    const bf16* __restrict__ Ah, const bf16* __restrict__ Al, int lda, long long sA,
    const bf16* __restrict__ Bh, const bf16* __restrict__ Bl, int ldb, long long sB,
    float* Cf, bf16* Ch, bf16* Cl, bf16* Ch2, bf16* Cl2, int ldc, long long sC,
    int K, int epi, int skipm, int trik, int fuse3)
{
    constexpr int WNC = 8 / WMC;
    constexpr int WM = 128 / WMC;
    constexpr int WN = BN / WNC;
    constexpr int MF = WM / 16;
    constexpr int NF = WN / 8;
    // stage layout: A 128 rows x 128B = 16KB, B BN rows x 128B
    constexpr int S_A = 0;
    constexpr int S_B = 16384;
    constexpr int STG = 16384 + BN * 128;

    int i0 = blockIdx.y * 128;
    int n0 = blockIdx.x * BN;
    int z = blockIdx.z;

    if (fuse3) {
        int comp = z % 3;
        int h = z / 3;
        skipm = (comp == 1) ? 2 : 1;
        epi = (comp == 0) ? 2 : ((comp == 1) ? 3 : 0);
        if (skipm == 1 && n0 > i0) return;
        if (skipm == 2 && n0 < i0) return;
        int aoff = (comp == 1) ? 0 : 3072;
        int boff = (comp == 0) ? 2048 : ((comp == 1) ? 1024 : 4096);
        Ah += h * 64 + aoff;
        Al += h * 64 + aoff;
        Bh += h * 64 + boff;
        Bl += h * 64 + boff;
        long long hs = (long long)h * HSLL;
        if (comp == 2) {
            Cf += hs;
        } else if (comp == 0) {
            Ch += hs;
            Cl += hs;
        } else {
            Ch = Ch2 + hs;
            Cl = Cl2 + hs;
        }
    } else {
        if (skipm == 1 && n0 > i0) return;
        if (skipm == 2 && n0 < i0) return;
        Ah += (long long)z * sA;
        Al += (long long)z * sA;
        Bh += (long long)z * sB;
        Bl += (long long)z * sB;
        if (Cf) Cf += (long long)z * sC;
        if (Ch) {
            Ch += (long long)z * sC;
            Cl += (long long)z * sC;
        }
    }

    int kbeg = 0;
    int kend = K;
    if (trik == 1) {
        kbeg = n0;
        kend = i0 + 128;
        if (kend > K) kend = K;
    } else if (trik == 2) {
        kend = i0 + 128;
        if (kend > K) kend = K;
    } else if (trik == 3) {
        int seg = blockIdx.x;
        n0 = 0;
        kend = i0 + 128;
        if (kend > K) kend = K;
        kbeg = seg * 512;
        if (kbeg >= kend) return;
        if (kend > kbeg + 512) kend = kbeg + 512;
        Cf += (long long)seg * (NSEQ * DIM);
    }
    int nch = (kend - kbeg + 31) >> 5;

    extern __shared__ __align__(1024) char smem[];
    uint32_t sb = smem_u32(smem);
    int tid = threadIdx.x;
    int wid = tid >> 5;
    int lane = tid & 31;
    int wm = wid % WMC;
    int wn = wid / WMC;

    auto stage_chunk = [&](int buf, int kt) {
        uint32_t base = sb + buf * STG;
        for (int u = tid; u < 512; u += 256) {
            int r = u >> 2;
            int kb = u & 3;
            long long go = (long long)(i0 + r) * lda + kt + kb * 8;
            uint32_t off = ((uint32_t)r << 7) | ((uint32_t)kb << 4);
            cpa16(base + S_A + sw128(off), Ah + go);
            cpa16(base + S_A + sw128(off + 64), Al + go);
        }
        for (int u = tid; u < BN * 4; u += 256) {
            int r = u >> 2;
            int kb = u & 3;
            long long go = (long long)(n0 + r) * ldb + kt + kb * 8;
            uint32_t off = ((uint32_t)r << 7) | ((uint32_t)kb << 4);
            cpa16(base + S_B + sw128(off), Bh + go);
            cpa16(base + S_B + sw128(off + 64), Bl + go);
        }
    };

    float acc[MF][NF][4];
    #pragma unroll
    for (int a = 0; a < MF; a++)
        #pragma unroll
        for (int b = 0; b < NF; b++)
            #pragma unroll
            for (int c = 0; c < 4; c++)
                acc[a][b][c] = 0.f;

    stage_chunk(0, kbeg);
    CP_COMMIT();

    for (int t = 0; t < nch; t++) {
        if (t + 1 < nch) {
            stage_chunk((t + 1) & 1, kbeg + (t + 1) * 32);
            CP_COMMIT();
            CP_WAIT1();
        } else {
            CP_WAIT0();
        }
        __syncthreads();

        uint32_t cbase = sb + (t & 1) * STG;
        #pragma unroll
        for (int ks = 0; ks < 2; ks++) {
            int g = lane >> 3;
            int rowin = lane & 7;
            // A fragments: x4 per mf (16m x 16k), hi and lo
            int kbA = ks * 32 + (g >> 1) * 16;
            uint32_t ahf[MF][4], alf[MF][4];
            #pragma unroll
            for (int mf = 0; mf < MF; mf++) {
                int r = wm * WM + mf * 16 + (g & 1) * 8 + rowin;
                uint32_t off = ((uint32_t)r << 7) + (uint32_t)kbA;
                ldm4(ahf[mf], cbase + S_A + sw128(off));
                ldm4(alf[mf], cbase + S_A + sw128(off + 64));
            }
            // B fragments: x4 loads a PAIR of n8 tiles (nf, nf+1)
            int kbB = ks * 32 + ((lane >> 3) & 1) * 16;
            int rowB = ((lane >> 4) & 1) * 8 + rowin;
            uint32_t bhf[NF][2], blf[NF][2];
            #pragma unroll
            for (int nfp = 0; nfp < NF; nfp += 2) {
                int r = wn * WN + nfp * 8 + rowB;
                uint32_t off = ((uint32_t)r << 7) + (uint32_t)kbB;
                uint32_t q[4];
                ldm4(q, cbase + S_B + sw128(off));
                bhf[nfp][0] = q[0]; bhf[nfp][1] = q[1];
                bhf[nfp + 1][0] = q[2]; bhf[nfp + 1][1] = q[3];
                ldm4(q, cbase + S_B + sw128(off + 64));
                blf[nfp][0] = q[0]; blf[nfp][1] = q[1];
                blf[nfp + 1][0] = q[2]; blf[nfp + 1][1] = q[3];
            }
            #pragma unroll
            for (int mf = 0; mf < MF; mf++) {
                #pragma unroll
                for (int nf = 0; nf < NF; nf++) {
                    mma16816(acc[mf][nf], ahf[mf], bhf[nf]);
                    mma16816(acc[mf][nf], ahf[mf], blf[nf]);
                    mma16816(acc[mf][nf], alf[mf], bhf[nf]);
                }
            }
        }
        __syncthreads();
    }

    // epilogue from register fragments (vectorized 2-column stores)
    int crow = lane >> 2;
    int ccol = (lane & 3) * 2;
    #pragma unroll
    for (int mf = 0; mf < MF; mf++) {
        #pragma unroll
        for (int nf = 0; nf < NF; nf++) {
            #pragma unroll
            for (int c2 = 0; c2 < 2; c2++) {
                int gi = i0 + wm * WM + mf * 16 + crow + c2 * 8;
                int gj = n0 + wn * WN + nf * 8 + ccol;
                float v0 = acc[mf][nf][c2 * 2];
                float v1 = acc[mf][nf][c2 * 2 + 1];
                long long idx = (long long)gi * ldc + gj;
                if (epi == 0) {
                    float2 f2;
                    f2.x = v0;
                    f2.y = v1;
                    *(float2*)(Cf + idx) = f2;
                } else if (epi == 6) {
                    float2 f2;
                    f2.x = v0 / (1.f + expf(-v0));
                    f2.y = v1 / (1.f + expf(-v1));
                    *(float2*)(Cf + idx) = f2;
                } else {
                    if (epi == 1) {
                        int c0 = gj >> 10;
                        int c1 = (gj + 1) >> 10;
                        if (c0 == 0 || c0 == 3) v0 *= 0.125f;
                        if (c1 == 0 || c1 == 3) v1 *= 0.125f;
                    } else if (epi == 2) {
                        v0 = (gj <= gi) ? v0 : 0.f;
                        v1 = (gj + 1 <= gi) ? v1 : 0.f;
                    } else if (epi == 3) {
                        v0 = (gj > gi) ? (1.f / (1.f + expf(-v0))) : 0.f;
                        v1 = (gj + 1 > gi) ? (1.f / (1.f + expf(-v1))) : 0.f;
                    }
                    bf16 h0 = f2bf(v0);
                    bf16 h1 = f2bf(v1);
                    uint32_t hp = (uint32_t)h0 | ((uint32_t)h1 << 16);
                    uint32_t lp = (uint32_t)f2bf(v0 - bf2f(h0)) | ((uint32_t)f2bf(v1 - bf2f(h1)) << 16);
                    *(uint32_t*)(Ch + idx) = hp;
                    *(uint32_t*)(Cl + idx) = lp;
                }
            }
        }
    }
}

// ---------------- merged split fp32 -> (hi, lo) bf16 for 3 tensors ----------------
__global__ void split3_kernel(const float* s0, bf16* h0, bf16* l0, int n0,
                              const float* s1, bf16* h1, bf16* l1, int n1,
                              const float* s2, bf16* h2, bf16* l2, int n2)
{
    const float* s;
    bf16* h;
    bf16* l;
    int n4;
    if (blockIdx.y == 0) { s = s0; h = h0; l = l0; n4 = n0; }
    else if (blockIdx.y == 1) { s = s1; h = h1; l = l1; n4 = n1; }
    else { s = s2; h = h2; l = l2; n4 = n2; }
    int i = blockIdx.x * 256 + threadIdx.x;
    if (i < n4) {
        float4 v = ((const float4*)s)[i];
        float vv[4];
        vv[0] = v.x; vv[1] = v.y; vv[2] = v.z; vv[3] = v.w;
        for (int k = 0; k < 4; k++) {
            bf16 hh = f2bf(vv[k]);
            h[i * 4 + k] = hh;
            l[i * 4 + k] = f2bf(vv[k] - bf2f(hh));
        }
    }
}

// ---------------- transpose vc: [n][5120 + c] -> [c][n] ----------------
__global__ void transpose_vc(const bf16* __restrict__ qh, const bf16* __restrict__ ql,
                             bf16* __restrict__ vth, bf16* __restrict__ vtl)
{
    __shared__ bf16 th[32][33];
    __shared__ bf16 tl[32][33];
    int c0 = blockIdx.x * 32;
    int n0 = blockIdx.y * 32;
    int tx = threadIdx.x;
    int ty = threadIdx.y;
    for (int r = ty; r < 32; r += 8) {
        th[r][tx] = qh[(long long)(n0 + r) * QKV6 + 5120 + c0 + tx];
        tl[r][tx] = ql[(long long)(n0 + r) * QKV6 + 5120 + c0 + tx];
    }
    __syncthreads();
    for (int r = ty; r < 32; r += 8) {
        vth[(long long)(c0 + r) * NSEQ + n0 + tx] = th[tx][r];
        vtl[(long long)(c0 + r) * NSEQ + n0 + tx] = tl[tx][r];
    }
}

// ---------------- softmax(sc - su_presilu) over j<=i -> attn bf16 pair, vectorized ----------------
__global__ void softmax_kernel(const float* __restrict__ sc, const float* __restrict__ su,
                               bf16* __restrict__ ah, bf16* __restrict__ al, int n)
{
    int i = blockIdx.x;
    int hh = blockIdx.y;
    long long base = ((long long)hh * n + i) * (long long)n;
    const float* scr = sc + base;
    const float* sur = su + base;
    bf16* ahr = ah + base;
    bf16* alr = al + base;

    int tid = threadIdx.x;
    const int NT = 256;
    float vals[8];
    int np = 0;
    float lmax = -INFINITY;
    for (int j = tid * 4; j <= i; j += NT * 4) {
        float4 s4 = *(const float4*)(scr + j);
        float4 u4 = *(const float4*)(sur + j);
        float v[4];
        v[0] = s4.x - u4.x;
        v[1] = s4.y - u4.y;
        v[2] = s4.z - u4.z;
        v[3] = s4.w - u4.w;
        #pragma unroll
        for (int e = 0; e < 4; e++) {
            if (j + e > i) v[e] = -INFINITY;
            vals[np * 4 + e] = v[e];
            lmax = fmaxf(lmax, v[e]);
        }
        np++;
    }

    __shared__ float red[33];
    for (int o = 16; o > 0; o >>= 1) lmax = fmaxf(lmax, __shfl_xor_sync(0xffffffffu, lmax, o));
    if ((tid & 31) == 0) red[tid >> 5] = lmax;
    __syncthreads();
    if (tid == 0) {
        float m0 = red[0];
        for (int w = 1; w < NT / 32; w++) m0 = fmaxf(m0, red[w]);
        red[32] = m0;
    }
    __syncthreads();
    float m = red[32];
    __syncthreads();

    float lsum = 0.f;
    for (int p = 0; p < np; p++) {
        #pragma unroll
        for (int e = 0; e < 4; e++) {
            float ex = expf(vals[p * 4 + e] - m);
            vals[p * 4 + e] = ex;
            lsum += ex;
        }
    }
    for (int o = 16; o > 0; o >>= 1) lsum += __shfl_xor_sync(0xffffffffu, lsum, o);
    if ((tid & 31) == 0) red[tid >> 5] = lsum;
    __syncthreads();
    if (tid == 0) {
        float s0 = 0.f;
        for (int w = 0; w < NT / 32; w++) s0 += red[w];
        red[32] = s0;
    }
    __syncthreads();
    float inv = 1.f / red[32];

    int p = 0;
    for (int j = tid * 4; j <= i; j += NT * 4, p++) {
        float v0 = vals[p * 4 + 0] * inv;
        float v1 = vals[p * 4 + 1] * inv;
        float v2 = vals[p * 4 + 2] * inv;
        float v3 = vals[p * 4 + 3] * inv;
        bf16 h0 = f2bf(v0), h1 = f2bf(v1), h2 = f2bf(v2), h3 = f2bf(v3);
        uint2 hp, lp;
        hp.x = (uint32_t)h0 | ((uint32_t)h1 << 16);
        hp.y = (uint32_t)h2 | ((uint32_t)h3 << 16);
        lp.x = (uint32_t)f2bf(v0 - bf2f(h0)) | ((uint32_t)f2bf(v1 - bf2f(h1)) << 16);
        lp.y = (uint32_t)f2bf(v2 - bf2f(h2)) | ((uint32_t)f2bf(v3 - bf2f(h3)) << 16);
        *(uint2*)(ahr + j) = hp;
        *(uint2*)(alr + j) = lp;
    }
    // zero-fill from next 4-pack through the 128-tile boundary
    int jz = ((i >> 2) + 1) << 2;
    int jend = (((i >> 7) + 1) << 7);
    uint2 zz;
    zz.x = 0;
    zz.y = 0;
    for (int j = jz + tid * 4; j < jend; j += NT * 4) {
        *(uint2*)(ahr + j) = zz;
        *(uint2*)(alr + j) = zz;
    }
}

// ---------------- reduce split-K partials -> o split pair ----------------
__global__ void reduce_split(const float* __restrict__ op, bf16* __restrict__ oh,
                             bf16* __restrict__ ol)
{
    int idx = blockIdx.x * 256 + threadIdx.x;   // one thread = 2 elements
    int e = idx * 2;
    int n = e / DIM;   // sequence row
    int limit = ((n >> 7) + 1) * 128;           // causal kend for this row's tile
    int nseg = (limit + 511) >> 9;              // live segments
    float2 s = *(const float2*)(op + e);
    for (int g = 1; g < nseg; g++) {
        float2 t = *(const float2*)(op + (size_t)g * (NSEQ * DIM) + e);
        s.x += t.x;
        s.y += t.y;
    }
    bf16 h0 = f2bf(s.x);
    bf16 h1 = f2bf(s.y);
    uint32_t hp = (uint32_t)h0 | ((uint32_t)h1 << 16);
    uint32_t lp = (uint32_t)f2bf(s.x - bf2f(h0)) | ((uint32_t)f2bf(s.y - bf2f(h1)) << 16);
    *(uint32_t*)(oh + e) = hp;
    *(uint32_t*)(ol + e) = lp;
}

extern "C" void kernel_launch(void* const* d_in, const int* in_sizes, int n_in,
                              void* d_out, int out_size)
{
    const float* x     = (const float*)d_in[0];
    const float* w_qkv = (const float*)d_in[1];
    const float* w_out = (const float*)d_in[2];
    float* out = (float*)d_out;

    bf16 *xh, *xl, *wqh, *wql, *woh, *wol, *qh, *ql, *vth, *vtl;
    bf16 *t1h, *t1l, *sgh, *sgl, *ah, *al, *oh, *ol;
    float *sc, *su, *op;
    cudaGetSymbolAddress((void**)&xh, g_xh);
    cudaGetSymbolAddress((void**)&xl, g_xl);
    cudaGetSymbolAddress((void**)&wqh, g_wqh);
    cudaGetSymbolAddress((void**)&wql, g_wql);
    cudaGetSymbolAddress((void**)&woh, g_woh);
    cudaGetSymbolAddress((void**)&wol, g_wol);
    cudaGetSymbolAddress((void**)&qh, g_qh);
    cudaGetSymbolAddress((void**)&ql, g_ql);
    cudaGetSymbolAddress((void**)&vth, g_vth);
    cudaGetSymbolAddress((void**)&vtl, g_vtl);
    cudaGetSymbolAddress((void**)&t1h, g_t1h);
    cudaGetSymbolAddress((void**)&t1l, g_t1l);
    cudaGetSymbolAddress((void**)&sgh, g_sgh);
    cudaGetSymbolAddress((void**)&sgl, g_sgl);
    cudaGetSymbolAddress((void**)&sc, g_sc);
    cudaGetSymbolAddress((void**)&su, g_su);
    cudaGetSymbolAddress((void**)&ah, g_ah);
    cudaGetSymbolAddress((void**)&al, g_al);
    cudaGetSymbolAddress((void**)&op, g_op);
    cudaGetSymbolAddress((void**)&oh, g_oh);
    cudaGetSymbolAddress((void**)&ol, g_ol);

    const int SMT128 = 2 * (16384 + 128 * 128);  // 65536
    const int SMT64  = 2 * (16384 + 64 * 128);   // 49152
    cudaFuncSetAttribute(mma_gemm<128, 2>, cudaFuncAttributeMaxDynamicSharedMemorySize, SMT128);
    cudaFuncSetAttribute(mma_gemm<64, 4>, cudaFuncAttributeMaxDynamicSharedMemorySize, SMT64);

    // splits (merged: x, w_qkv, w_out)
    {
        int nx = NSEQ * DIM / 4;       // 524288
        int nq = QKV6 * DIM / 4;       // 1572864
        int no = DIM * DIM / 4;        // 262144
        int maxb = (nq + 255) / 256;
        split3_kernel<<<dim3(maxb, 3), 256>>>(x, xh, xl, nx,
                                              w_qkv, wqh, wql, nq,
                                              w_out, woh, wol, no);
    }

    // 1) qkvs = x @ w_qkv^T (scale qu,qc by 0.125), split pair
    mma_gemm<128, 2><<<dim3(QKV6 / 128, NSEQ / 128, 1), 256, SMT128>>>(
        xh, xl, DIM, 0, wqh, wql, DIM, 0,
        (float*)0, qh, ql, (bf16*)0, (bf16*)0, QKV6, 0,
        DIM, 1, 0, 0, 0);

    // 1b) transpose vc -> [64][N] per head
    transpose_vc<<<dim3(DIM / 32, NSEQ / 32), dim3(32, 8)>>>(qh, ql, vth, vtl);

    // 2-4 fused) comp0: term1 = qc@vu^T (epi2); comp1: sig = sigmoid(qu@ku^T) (epi3);
    //            comp2: Sc = qc@kc^T (epi0). z = h*3+comp.
    mma_gemm<128, 2><<<dim3(16, 16, HEADS * 3), 256, SMT128>>>(
        qh, ql, QKV6, 0, qh, ql, QKV6, 0,
        sc, t1h, t1l, sgh, sgl, NSEQ, 0,
        64, 0, 0, 0, /*fuse3*/1);

    // 5) su = silu(term1 @ sig^T), triangular k-range (epi 6)
    mma_gemm<128, 2><<<dim3(16, 16, HEADS), 256, SMT128>>>(
        t1h, t1l, NSEQ, HSLL, sgh, sgl, NSEQ, HSLL,
        su, (bf16*)0, (bf16*)0, (bf16*)0, (bf16*)0, NSEQ, HSLL,
        NSEQ, 6, 1, 1, 0);

    // 6) softmax(sc - su) -> attn split pair (su already silu'd)
    softmax_kernel<<<dim3(NSEQ, HEADS), 256>>>(sc, su, ah, al, NSEQ);

    // 7) split-K attn@vc: partials into op[seg], balanced across 4 segments
    mma_gemm<64, 4><<<dim3(4, 16, HEADS), 256, SMT64>>>(
        ah, al, NSEQ, HSLL, vth, vtl, NSEQ, 64LL * NSEQ,
        op, (bf16*)0, (bf16*)0, (bf16*)0, (bf16*)0, DIM, 64,
        NSEQ, 0, 0, 3, 0);

    // 7b) reduce partials -> oh/ol split pair
    reduce_split<<<NSEQ * DIM / 512, 256>>>(op, oh, ol);

    // 8) out = o @ w_out^T, fp32
    mma_gemm<128, 2><<<dim3(DIM / 128, NSEQ / 128, 1), 256, SMT128>>>(
        oh, ol, HEADS * 64, 0, woh, wol, HEADS * 64, 0,
        out, (bf16*)0, (bf16*)0, (bf16*)0, (bf16*)0, DIM, 0,
        HEADS * 64, 0, 0, 0, 0);
}

// round 15
// speedup vs baseline: 1.2396x; 1.0260x over previous
#include <cuda_runtime.h>
#include <math.h>
#include <stdint.h>

#define NSEQ 2048
#define DIM  1024
#define HEADS 16
#define QKV6 6144
#define HSLL ((long long)NSEQ * NSEQ)

typedef unsigned short bf16;

// ---------------- device scratch (allocation-free) ----------------
__device__ bf16 g_xh[NSEQ * DIM];
__device__ bf16 g_xl[NSEQ * DIM];
__device__ bf16 g_wqh[QKV6 * DIM];
__device__ bf16 g_wql[QKV6 * DIM];
__device__ bf16 g_woh[DIM * DIM];
__device__ bf16 g_wol[DIM * DIM];
__device__ bf16 g_qh[NSEQ * QKV6];
__device__ bf16 g_ql[NSEQ * QKV6];
__device__ bf16 g_vth[DIM * NSEQ];   // vc transposed: [h*64+d][n]
__device__ bf16 g_vtl[DIM * NSEQ];
__device__ bf16 g_t1h[(size_t)HEADS * NSEQ * NSEQ];
__device__ bf16 g_t1l[(size_t)HEADS * NSEQ * NSEQ];
__device__ bf16 g_sgh[(size_t)HEADS * NSEQ * NSEQ];
__device__ bf16 g_sgl[(size_t)HEADS * NSEQ * NSEQ];
__device__ float g_sc[(size_t)HEADS * NSEQ * NSEQ];
__device__ float g_su[(size_t)HEADS * NSEQ * NSEQ];
__device__ bf16 g_ah[(size_t)HEADS * NSEQ * NSEQ];
__device__ bf16 g_al[(size_t)HEADS * NSEQ * NSEQ];
__device__ float g_op[4 * NSEQ * DIM];   // split-K partials for attn@vc
__device__ bf16 g_oh[NSEQ * DIM];
__device__ bf16 g_ol[NSEQ * DIM];

// ---------------- helpers ----------------
__device__ __forceinline__ bf16 f2bf(float f) {
    bf16 h;
    asm("cvt.rn.bf16.f32 %0, %1;" : "=h"(h) : "f"(f));
    return h;
}
__device__ __forceinline__ float bf2f(bf16 h) {
    return __uint_as_float(((unsigned int)h) << 16);
}

__device__ __forceinline__ uint32_t smem_u32(const void* p) {
    uint32_t a;
    asm("{ .reg .u64 t; cvta.to.shared.u64 t, %1; cvt.u32.u64 %0, t; }" : "=r"(a) : "l"(p));
    return a;
}

__device__ __forceinline__ void cpa16(uint32_t saddr, const void* g) {
    asm volatile("cp.async.cg.shared.global [%0], [%1], 16;" :: "r"(saddr), "l"(g));
}
#define CP_COMMIT() asm volatile("cp.async.commit_group;" ::: "memory")
#define CP_WAIT0() asm volatile("cp.async.wait_group 0;" ::: "memory")
#define CP_WAIT1() asm volatile("cp.async.wait_group 1;" ::: "memory")

__device__ __forceinline__ void ldm4(uint32_t* r, uint32_t addr) {
    asm volatile("ldmatrix.sync.aligned.m8n8.x4.shared.b16 {%0,%1,%2,%3}, [%4];"
        : "=r"(r[0]), "=r"(r[1]), "=r"(r[2]), "=r"(r[3]) : "r"(addr));
}

__device__ __forceinline__ void mma16816(float* d, const uint32_t* a, const uint32_t* b) {
    asm volatile(
        "mma.sync.aligned.m16n8k16.row.col.f32.bf16.bf16.f32 "
        "{%0,%1,%2,%3}, {%4,%5,%6,%7}, {%8,%9}, {%0,%1,%2,%3};"
        : "+f"(d[0]), "+f"(d[1]), "+f"(d[2]), "+f"(d[3])
        : "r"(a[0]), "r"(a[1]), "r"(a[2]), "r"(a[3]), "r"(b[0]), "r"(b[1]));
}

// SW128 swizzle for 128-byte rows: XOR bits[6:4] with row bits[2:0]
__device__ __forceinline__ uint32_t sw128(uint32_t off) {
    return off ^ ((off >> 3) & 0x70);
}

// ---------------- warp-MMA GEMM engine (unchanged R14 winner) ----------------
template<int BN, int WMC>
__global__ void __launch_bounds__(256, 2) mma_gemm(
    const bf16* __restrict__ Ah, const bf16* __restrict__ Al, int lda, long long sA,
    const bf16* __restrict__ Bh, const bf16* __restrict__ Bl, int ldb, long long sB,
    float* Cf, bf16* Ch, bf16* Cl, bf16* Ch2, bf16* Cl2, int ldc, long long sC,
    int K, int epi, int skipm, int trik, int fuse3)
{
    constexpr int WNC = 8 / WMC;
    constexpr int WM = 128 / WMC;
    constexpr int WN = BN / WNC;
    constexpr int MF = WM / 16;
    constexpr int NF = WN / 8;
    constexpr int S_A = 0;
    constexpr int S_B = 16384;
    constexpr int STG = 16384 + BN * 128;

    int i0 = blockIdx.y * 128;
    int n0 = blockIdx.x * BN;
    int z = blockIdx.z;

    if (fuse3) {
        int comp = z % 3;
        int h = z / 3;
        skipm = (comp == 1) ? 2 : 1;
        epi = (comp == 0) ? 2 : ((comp == 1) ? 3 : 0);
        if (skipm == 1 && n0 > i0) return;
        if (skipm == 2 && n0 < i0) return;
        int aoff = (comp == 1) ? 0 : 3072;
        int boff = (comp == 0) ? 2048 : ((comp == 1) ? 1024 : 4096);
        Ah += h * 64 + aoff;
        Al += h * 64 + aoff;
        Bh += h * 64 + boff;
        Bl += h * 64 + boff;
        long long hs = (long long)h * HSLL;
        if (comp == 2) {
            Cf += hs;
        } else if (comp == 0) {
            Ch += hs;
            Cl += hs;
        } else {
            Ch = Ch2 + hs;
            Cl = Cl2 + hs;
        }
    } else {
        if (skipm == 1 && n0 > i0) return;
        if (skipm == 2 && n0 < i0) return;
        Ah += (long long)z * sA;
        Al += (long long)z * sA;
        Bh += (long long)z * sB;
        Bl += (long long)z * sB;
        if (Cf) Cf += (long long)z * sC;
        if (Ch) {
            Ch += (long long)z * sC;
            Cl += (long long)z * sC;
        }
    }

    int kbeg = 0;
    int kend = K;
    if (trik == 1) {
        kbeg = n0;
        kend = i0 + 128;
        if (kend > K) kend = K;
    } else if (trik == 2) {
        kend = i0 + 128;
        if (kend > K) kend = K;
    } else if (trik == 3) {
        int seg = blockIdx.x;
        n0 = 0;
        kend = i0 + 128;
        if (kend > K) kend = K;
        kbeg = seg * 512;
        if (kbeg >= kend) return;
        if (kend > kbeg + 512) kend = kbeg + 512;
        Cf += (long long)seg * (NSEQ * DIM);
    }
    int nch = (kend - kbeg + 31) >> 5;

    extern __shared__ __align__(1024) char smem[];
    uint32_t sb = smem_u32(smem);
    int tid = threadIdx.x;
    int wid = tid >> 5;
    int lane = tid & 31;
    int wm = wid % WMC;
    int wn = wid / WMC;

    auto stage_chunk = [&](int buf, int kt) {
        uint32_t base = sb + buf * STG;
        for (int u = tid; u < 512; u += 256) {
            int r = u >> 2;
            int kb = u & 3;
            long long go = (long long)(i0 + r) * lda + kt + kb * 8;
            uint32_t off = ((uint32_t)r << 7) | ((uint32_t)kb << 4);
            cpa16(base + S_A + sw128(off), Ah + go);
            cpa16(base + S_A + sw128(off + 64), Al + go);
        }
        for (int u = tid; u < BN * 4; u += 256) {
            int r = u >> 2;
            int kb = u & 3;
            long long go = (long long)(n0 + r) * ldb + kt + kb * 8;
            uint32_t off = ((uint32_t)r << 7) | ((uint32_t)kb << 4);
            cpa16(base + S_B + sw128(off), Bh + go);
            cpa16(base + S_B + sw128(off + 64), Bl + go);
        }
    };

    float acc[MF][NF][4];
    #pragma unroll
    for (int a = 0; a < MF; a++)
        #pragma unroll
        for (int b = 0; b < NF; b++)
            #pragma unroll
            for (int c = 0; c < 4; c++)
                acc[a][b][c] = 0.f;

    stage_chunk(0, kbeg);
    CP_COMMIT();

    for (int t = 0; t < nch; t++) {
        if (t + 1 < nch) {
            stage_chunk((t + 1) & 1, kbeg + (t + 1) * 32);
            CP_COMMIT();
            CP_WAIT1();
        } else {
            CP_WAIT0();
        }
        __syncthreads();

        uint32_t cbase = sb + (t & 1) * STG;
        #pragma unroll
        for (int ks = 0; ks < 2; ks++) {
            int g = lane >> 3;
            int rowin = lane & 7;
            int kbA = ks * 32 + (g >> 1) * 16;
            uint32_t ahf[MF][4], alf[MF][4];
            #pragma unroll
            for (int mf = 0; mf < MF; mf++) {
                int r = wm * WM + mf * 16 + (g & 1) * 8 + rowin;
                uint32_t off = ((uint32_t)r << 7) + (uint32_t)kbA;
                ldm4(ahf[mf], cbase + S_A + sw128(off));
                ldm4(alf[mf], cbase + S_A + sw128(off + 64));
            }
            int kbB = ks * 32 + ((lane >> 3) & 1) * 16;
            int rowB = ((lane >> 4) & 1) * 8 + rowin;
            uint32_t bhf[NF][2], blf[NF][2];
            #pragma unroll
            for (int nfp = 0; nfp < NF; nfp += 2) {
                int r = wn * WN + nfp * 8 + rowB;
                uint32_t off = ((uint32_t)r << 7) + (uint32_t)kbB;
                uint32_t q[4];
                ldm4(q, cbase + S_B + sw128(off));
                bhf[nfp][0] = q[0]; bhf[nfp][1] = q[1];
                bhf[nfp + 1][0] = q[2]; bhf[nfp + 1][1] = q[3];
                ldm4(q, cbase + S_B + sw128(off + 64));
                blf[nfp][0] = q[0]; blf[nfp][1] = q[1];
                blf[nfp + 1][0] = q[2]; blf[nfp + 1][1] = q[3];
            }
            #pragma unroll
            for (int mf = 0; mf < MF; mf++) {
                #pragma unroll
                for (int nf = 0; nf < NF; nf++) {
                    mma16816(acc[mf][nf], ahf[mf], bhf[nf]);
                    mma16816(acc[mf][nf], ahf[mf], blf[nf]);
                    mma16816(acc[mf][nf], alf[mf], bhf[nf]);
                }
            }
        }
        __syncthreads();
    }

    int crow = lane >> 2;
    int ccol = (lane & 3) * 2;
    #pragma unroll
    for (int mf = 0; mf < MF; mf++) {
        #pragma unroll
        for (int nf = 0; nf < NF; nf++) {
            #pragma unroll
            for (int c2 = 0; c2 < 2; c2++) {
                int gi = i0 + wm * WM + mf * 16 + crow + c2 * 8;
                int gj = n0 + wn * WN + nf * 8 + ccol;
                float v0 = acc[mf][nf][c2 * 2];
                float v1 = acc[mf][nf][c2 * 2 + 1];
                long long idx = (long long)gi * ldc + gj;
                if (epi == 0) {
                    float2 f2;
                    f2.x = v0;
                    f2.y = v1;
                    *(float2*)(Cf + idx) = f2;
                } else if (epi == 6) {
                    float2 f2;
                    f2.x = v0 / (1.f + expf(-v0));
                    f2.y = v1 / (1.f + expf(-v1));
                    *(float2*)(Cf + idx) = f2;
                } else {
                    if (epi == 1) {
                        int c0 = gj >> 10;
                        int c1 = (gj + 1) >> 10;
                        if (c0 == 0 || c0 == 3) v0 *= 0.125f;
                        if (c1 == 0 || c1 == 3) v1 *= 0.125f;
                    } else if (epi == 2) {
                        v0 = (gj <= gi) ? v0 : 0.f;
                        v1 = (gj + 1 <= gi) ? v1 : 0.f;
                    } else if (epi == 3) {
                        v0 = (gj > gi) ? (1.f / (1.f + expf(-v0))) : 0.f;
                        v1 = (gj + 1 > gi) ? (1.f / (1.f + expf(-v1))) : 0.f;
                    }
                    bf16 h0 = f2bf(v0);
                    bf16 h1 = f2bf(v1);
                    uint32_t hp = (uint32_t)h0 | ((uint32_t)h1 << 16);
                    uint32_t lp = (uint32_t)f2bf(v0 - bf2f(h0)) | ((uint32_t)f2bf(v1 - bf2f(h1)) << 16);
                    *(uint32_t*)(Ch + idx) = hp;
                    *(uint32_t*)(Cl + idx) = lp;
                }
            }
        }
    }
}

// ---------------- panel score3: A staged once (K=64), loop 4 n-tiles with B double-buffer ----
// grid (4, 16, HEADS*3). comp0: term1 (lower, epi2); comp1: sig (upper incl diag, epi3);
// comp2: Sc (lower, fp32). MMA order per tile identical to the engine.
__global__ void __launch_bounds__(256, 2) score3_panel(
    const bf16* __restrict__ qh, const bf16* __restrict__ ql,
    float* __restrict__ sc, bf16* __restrict__ t1h, bf16* __restrict__ t1l,
    bf16* __restrict__ sgh, bf16* __restrict__ sgl)
{
    const int S_A = 0;        // 2 chunks x 16KB
    const int S_B0 = 32768;   // buf0: 2 chunks x 16KB
    const int S_B1 = 65536;   // buf1

    int comp = blockIdx.z % 3;
    int h = blockIdx.z / 3;
    int ti = blockIdx.y;
    int i0 = ti * 128;
    int lo, hi;
    if (comp == 1) {
        lo = blockIdx.x * 4;
        if (lo < ti) lo = ti;
        hi = blockIdx.x * 4 + 3;
    } else {
        lo = blockIdx.x * 4;
        hi = blockIdx.x * 4 + 3;
        if (hi > ti) hi = ti;
    }
    if (lo > hi) return;

    int aoff = (comp == 1) ? 0 : 3072;
    int boff = (comp == 0) ? 2048 : ((comp == 1) ? 1024 : 4096);
    const bf16* Ah = qh + h * 64 + aoff;
    const bf16* Al = ql + h * 64 + aoff;
    const bf16* Bh = qh + h * 64 + boff;
    const bf16* Bl = ql + h * 64 + boff;
    long long hs = (long long)h * HSLL;
    float* Cf = sc + hs;
    bf16* Ch;
    bf16* Cl;
    if (comp == 0) { Ch = t1h + hs; Cl = t1l + hs; }
    else { Ch = sgh + hs; Cl = sgl + hs; }

    extern __shared__ __align__(1024) char smem[];
    uint32_t sb = smem_u32(smem);
    int tid = threadIdx.x;
    int wid = tid >> 5;
    int lane = tid & 31;
    int wm = wid % 2;      // WMC=2 -> WM=64, MF=4
    int wn = wid / 2;      // WNC=4 -> WN=32, NF=4

    // stage A row-panel: both chunks of K=64
    for (int c = 0; c < 2; c++) {
        for (int u = tid; u < 512; u += 256) {
            int r = u >> 2;
            int kb = u & 3;
            long long go = (long long)(i0 + r) * QKV6 + c * 32 + kb * 8;
            uint32_t off = ((uint32_t)r << 7) | ((uint32_t)kb << 4);
            cpa16(sb + S_A + c * 16384 + sw128(off), Ah + go);
            cpa16(sb + S_A + c * 16384 + sw128(off + 64), Al + go);
        }
    }
    auto stage_B = [&](uint32_t bbase, int nt) {
        int n0 = nt * 128;
        for (int c = 0; c < 2; c++) {
            for (int u = tid; u < 512; u += 256) {
                int r = u >> 2;
                int kb = u & 3;
                long long go = (long long)(n0 + r) * QKV6 + c * 32 + kb * 8;
                uint32_t off = ((uint32_t)r << 7) | ((uint32_t)kb << 4);
                cpa16(bbase + c * 16384 + sw128(off), Bh + go);
                cpa16(bbase + c * 16384 + sw128(off + 64), Bl + go);
            }
        }
    };
    stage_B(sb + S_B0, lo);
    CP_COMMIT();

    int buf = 0;
    for (int nt = lo; nt <= hi; nt++) {
        if (nt + 1 <= hi) {
            stage_B(sb + (buf ? S_B0 : S_B1), nt + 1);
            CP_COMMIT();
            CP_WAIT1();
        } else {
            CP_WAIT0();
        }
        __syncthreads();

        float acc[4][4][4];
        #pragma unroll
        for (int a = 0; a < 4; a++)
            #pragma unroll
            for (int b = 0; b < 4; b++)
                #pragma unroll
                for (int c = 0; c < 4; c++)
                    acc[a][b][c] = 0.f;

        uint32_t bB = sb + (buf ? S_B1 : S_B0);
        #pragma unroll
        for (int c = 0; c < 2; c++) {
            uint32_t cA = sb + S_A + c * 16384;
            uint32_t cB = bB + c * 16384;
            #pragma unroll
            for (int ks = 0; ks < 2; ks++) {
                int g = lane >> 3;
                int rowin = lane & 7;
                int kbA = ks * 32 + (g >> 1) * 16;
                uint32_t ahf[4][4], alf[4][4];
                #pragma unroll
                for (int mf = 0; mf < 4; mf++) {
                    int r = wm * 64 + mf * 16 + (g & 1) * 8 + rowin;
                    uint32_t off = ((uint32_t)r << 7) + (uint32_t)kbA;
                    ldm4(ahf[mf], cA + sw128(off));
                    ldm4(alf[mf], cA + sw128(off + 64));
                }
                int kbB = ks * 32 + ((lane >> 3) & 1) * 16;
                int rowB = ((lane >> 4) & 1) * 8 + rowin;
                uint32_t bhf[4][2], blf[4][2];
                #pragma unroll
                for (int nfp = 0; nfp < 4; nfp += 2) {
                    int r = wn * 32 + nfp * 8 + rowB;
                    uint32_t off = ((uint32_t)r << 7) + (uint32_t)kbB;
                    uint32_t q[4];
                    ldm4(q, cB + sw128(off));
                    bhf[nfp][0] = q[0]; bhf[nfp][1] = q[1];
                    bhf[nfp + 1][0] = q[2]; bhf[nfp + 1][1] = q[3];
                    ldm4(q, cB + sw128(off + 64));
                    blf[nfp][0] = q[0]; blf[nfp][1] = q[1];
                    blf[nfp + 1][0] = q[2]; blf[nfp + 1][1] = q[3];
                }
                #pragma unroll
                for (int mf = 0; mf < 4; mf++) {
                    #pragma unroll
                    for (int nf = 0; nf < 4; nf++) {
                        mma16816(acc[mf][nf], ahf[mf], bhf[nf]);
                        mma16816(acc[mf][nf], ahf[mf], blf[nf]);
                        mma16816(acc[mf][nf], alf[mf], bhf[nf]);
                    }
                }
            }
        }
        __syncthreads();

        // epilogue for tile nt
        int n0 = nt * 128;
        int crow = lane >> 2;
        int ccol = (lane & 3) * 2;
        #pragma unroll
        for (int mf = 0; mf < 4; mf++) {
            #pragma unroll
            for (int nf = 0; nf < 4; nf++) {
                #pragma unroll
                for (int c2 = 0; c2 < 2; c2++) {
                    int gi = i0 + wm * 64 + mf * 16 + crow + c2 * 8;
                    int gj = n0 + wn * 32 + nf * 8 + ccol;
                    float v0 = acc[mf][nf][c2 * 2];
                    float v1 = acc[mf][nf][c2 * 2 + 1];
                    long long idx = (long long)gi * NSEQ + gj;
                    if (comp == 2) {
                        float2 f2;
                        f2.x = v0;
                        f2.y = v1;
                        *(float2*)(Cf + idx) = f2;
                    } else {
                        if (comp == 0) {
                            v0 = (gj <= gi) ? v0 : 0.f;
                            v1 = (gj + 1 <= gi) ? v1 : 0.f;
                        } else {
                            v0 = (gj > gi) ? (1.f / (1.f + expf(-v0))) : 0.f;
                            v1 = (gj + 1 > gi) ? (1.f / (1.f + expf(-v1))) : 0.f;
                        }
                        bf16 h0 = f2bf(v0);
                        bf16 h1 = f2bf(v1);
                        uint32_t hp = (uint32_t)h0 | ((uint32_t)h1 << 16);
                        uint32_t lp = (uint32_t)f2bf(v0 - bf2f(h0)) | ((uint32_t)f2bf(v1 - bf2f(h1)) << 16);
                        *(uint32_t*)(Ch + idx) = hp;
                        *(uint32_t*)(Cl + idx) = lp;
                    }
                }
            }
        }
        buf ^= 1;
    }
}

// ---------------- merged split fp32 -> (hi, lo) bf16 for 3 tensors ----------------
__global__ void split3_kernel(const float* s0, bf16* h0, bf16* l0, int n0,
                              const float* s1, bf16* h1, bf16* l1, int n1,
                              const float* s2, bf16* h2, bf16* l2, int n2)
{
    const float* s;
    bf16* h;
    bf16* l;
    int n4;
    if (blockIdx.y == 0) { s = s0; h = h0; l = l0; n4 = n0; }
    else if (blockIdx.y == 1) { s = s1; h = h1; l = l1; n4 = n1; }
    else { s = s2; h = h2; l = l2; n4 = n2; }
    int i = blockIdx.x * 256 + threadIdx.x;
    if (i < n4) {
        float4 v = ((const float4*)s)[i];
        float vv[4];
        vv[0] = v.x; vv[1] = v.y; vv[2] = v.z; vv[3] = v.w;
        for (int k = 0; k < 4; k++) {
            bf16 hh = f2bf(vv[k]);
            h[i * 4 + k] = hh;
            l[i * 4 + k] = f2bf(vv[k] - bf2f(hh));
        }
    }
}

// ---------------- transpose vc: [n][5120 + c] -> [c][n] ----------------
__global__ void transpose_vc(const bf16* __restrict__ qh, const bf16* __restrict__ ql,
                             bf16* __restrict__ vth, bf16* __restrict__ vtl)
{
    __shared__ bf16 th[32][33];
    __shared__ bf16 tl[32][33];
    int c0 = blockIdx.x * 32;
    int n0 = blockIdx.y * 32;
    int tx = threadIdx.x;
    int ty = threadIdx.y;
    for (int r = ty; r < 32; r += 8) {
        th[r][tx] = qh[(long long)(n0 + r) * QKV6 + 5120 + c0 + tx];
        tl[r][tx] = ql[(long long)(n0 + r) * QKV6 + 5120 + c0 + tx];
    }
    __syncthreads();
    for (int r = ty; r < 32; r += 8) {
        vth[(long long)(c0 + r) * NSEQ + n0 + tx] = th[tx][r];
        vtl[(long long)(c0 + r) * NSEQ + n0 + tx] = tl[tx][r];
    }
}

// ---------------- softmax(sc - su_presilu) over j<=i -> attn bf16 pair, vectorized ----------------
__global__ void softmax_kernel(const float* __restrict__ sc, const float* __restrict__ su,
                               bf16* __restrict__ ah, bf16* __restrict__ al, int n)
{
    int i = blockIdx.x;
    int hh = blockIdx.y;
    long long base = ((long long)hh * n + i) * (long long)n;
    const float* scr = sc + base;
    const float* sur = su + base;
    bf16* ahr = ah + base;
    bf16* alr = al + base;

    int tid = threadIdx.x;
    const int NT = 256;
    float vals[8];
    int np = 0;
    float lmax = -INFINITY;
    for (int j = tid * 4; j <= i; j += NT * 4) {
        float4 s4 = *(const float4*)(scr + j);
        float4 u4 = *(const float4*)(sur + j);
        float v[4];
        v[0] = s4.x - u4.x;
        v[1] = s4.y - u4.y;
        v[2] = s4.z - u4.z;
        v[3] = s4.w - u4.w;
        #pragma unroll
        for (int e = 0; e < 4; e++) {
            if (j + e > i) v[e] = -INFINITY;
            vals[np * 4 + e] = v[e];
            lmax = fmaxf(lmax, v[e]);
        }
        np++;
    }

    __shared__ float red[33];
    for (int o = 16; o > 0; o >>= 1) lmax = fmaxf(lmax, __shfl_xor_sync(0xffffffffu, lmax, o));
    if ((tid & 31) == 0) red[tid >> 5] = lmax;
    __syncthreads();
    if (tid == 0) {
        float m0 = red[0];
        for (int w = 1; w < NT / 32; w++) m0 = fmaxf(m0, red[w]);
        red[32] = m0;
    }
    __syncthreads();
    float m = red[32];
    __syncthreads();

    float lsum = 0.f;
    for (int p = 0; p < np; p++) {
        #pragma unroll
        for (int e = 0; e < 4; e++) {
            float ex = expf(vals[p * 4 + e] - m);
            vals[p * 4 + e] = ex;
            lsum += ex;
        }
    }
    for (int o = 16; o > 0; o >>= 1) lsum += __shfl_xor_sync(0xffffffffu, lsum, o);
    if ((tid & 31) == 0) red[tid >> 5] = lsum;
    __syncthreads();
    if (tid == 0) {
        float s0 = 0.f;
        for (int w = 0; w < NT / 32; w++) s0 += red[w];
        red[32] = s0;
    }
    __syncthreads();
    float inv = 1.f / red[32];

    int p = 0;
    for (int j = tid * 4; j <= i; j += NT * 4, p++) {
        float v0 = vals[p * 4 + 0] * inv;
        float v1 = vals[p * 4 + 1] * inv;
        float v2 = vals[p * 4 + 2] * inv;
        float v3 = vals[p * 4 + 3] * inv;
        bf16 h0 = f2bf(v0), h1 = f2bf(v1), h2 = f2bf(v2), h3 = f2bf(v3);
        uint2 hp, lp;
        hp.x = (uint32_t)h0 | ((uint32_t)h1 << 16);
        hp.y = (uint32_t)h2 | ((uint32_t)h3 << 16);
        lp.x = (uint32_t)f2bf(v0 - bf2f(h0)) | ((uint32_t)f2bf(v1 - bf2f(h1)) << 16);
        lp.y = (uint32_t)f2bf(v2 - bf2f(h2)) | ((uint32_t)f2bf(v3 - bf2f(h3)) << 16);
        *(uint2*)(ahr + j) = hp;
        *(uint2*)(alr + j) = lp;
    }
    int jz = ((i >> 2) + 1) << 2;
    int jend = (((i >> 7) + 1) << 7);
    uint2 zz;
    zz.x = 0;
    zz.y = 0;
    for (int j = jz + tid * 4; j < jend; j += NT * 4) {
        *(uint2*)(ahr + j) = zz;
        *(uint2*)(alr + j) = zz;
    }
}

// ---------------- reduce split-K partials -> o split pair ----------------
__global__ void reduce_split(const float* __restrict__ op, bf16* __restrict__ oh,
                             bf16* __restrict__ ol)
{
    int idx = blockIdx.x * 256 + threadIdx.x;
    int e = idx * 2;
    int n = e / DIM;
    int limit = ((n >> 7) + 1) * 128;
    int nseg = (limit + 511) >> 9;
    float2 s = *(const float2*)(op + e);
    for (int g = 1; g < nseg; g++) {
        float2 t = *(const float2*)(op + (size_t)g * (NSEQ * DIM) + e);
        s.x += t.x;
        s.y += t.y;
    }
    bf16 h0 = f2bf(s.x);
    bf16 h1 = f2bf(s.y);
    uint32_t hp = (uint32_t)h0 | ((uint32_t)h1 << 16);
    uint32_t lp = (uint32_t)f2bf(s.x - bf2f(h0)) | ((uint32_t)f2bf(s.y - bf2f(h1)) << 16);
    *(uint32_t*)(oh + e) = hp;
    *(uint32_t*)(ol + e) = lp;
}

extern "C" void kernel_launch(void* const* d_in, const int* in_sizes, int n_in,
                              void* d_out, int out_size)
{
    const float* x     = (const float*)d_in[0];
    const float* w_qkv = (const float*)d_in[1];
    const float* w_out = (const float*)d_in[2];
    float* out = (float*)d_out;

    bf16 *xh, *xl, *wqh, *wql, *woh, *wol, *qh, *ql, *vth, *vtl;
    bf16 *t1h, *t1l, *sgh, *sgl, *ah, *al, *oh, *ol;
    float *sc, *su, *op;
    cudaGetSymbolAddress((void**)&xh, g_xh);
    cudaGetSymbolAddress((void**)&xl, g_xl);
    cudaGetSymbolAddress((void**)&wqh, g_wqh);
    cudaGetSymbolAddress((void**)&wql, g_wql);
    cudaGetSymbolAddress((void**)&woh, g_woh);
    cudaGetSymbolAddress((void**)&wol, g_wol);
    cudaGetSymbolAddress((void**)&qh, g_qh);
    cudaGetSymbolAddress((void**)&ql, g_ql);
    cudaGetSymbolAddress((void**)&vth, g_vth);
    cudaGetSymbolAddress((void**)&vtl, g_vtl);
    cudaGetSymbolAddress((void**)&t1h, g_t1h);
    cudaGetSymbolAddress((void**)&t1l, g_t1l);
    cudaGetSymbolAddress((void**)&sgh, g_sgh);
    cudaGetSymbolAddress((void**)&sgl, g_sgl);
    cudaGetSymbolAddress((void**)&sc, g_sc);
    cudaGetSymbolAddress((void**)&su, g_su);
    cudaGetSymbolAddress((void**)&ah, g_ah);
    cudaGetSymbolAddress((void**)&al, g_al);
    cudaGetSymbolAddress((void**)&op, g_op);
    cudaGetSymbolAddress((void**)&oh, g_oh);
    cudaGetSymbolAddress((void**)&ol, g_ol);

    const int SMT128 = 2 * (16384 + 128 * 128);  // 65536
    const int SMT64  = 2 * (16384 + 64 * 128);   // 49152
    const int SMTP   = 98304;                    // panel: A 32KB + 2x B 32KB
    cudaFuncSetAttribute(mma_gemm<128, 2>, cudaFuncAttributeMaxDynamicSharedMemorySize, SMT128);
    cudaFuncSetAttribute(mma_gemm<64, 4>, cudaFuncAttributeMaxDynamicSharedMemorySize, SMT64);
    cudaFuncSetAttribute(score3_panel, cudaFuncAttributeMaxDynamicSharedMemorySize, SMTP);

    // splits (merged: x, w_qkv, w_out)
    {
        int nx = NSEQ * DIM / 4;
        int nq = QKV6 * DIM / 4;
        int no = DIM * DIM / 4;
        int maxb = (nq + 255) / 256;
        split3_kernel<<<dim3(maxb, 3), 256>>>(x, xh, xl, nx,
                                              w_qkv, wqh, wql, nq,
                                              w_out, woh, wol, no);
    }

    // 1) qkvs = x @ w_qkv^T (scale qu,qc by 0.125), split pair
    mma_gemm<128, 2><<<dim3(QKV6 / 128, NSEQ / 128, 1), 256, SMT128>>>(
        xh, xl, DIM, 0, wqh, wql, DIM, 0,
        (float*)0, qh, ql, (bf16*)0, (bf16*)0, QKV6, 0,
        DIM, 1, 0, 0, 0);

    // 1b) transpose vc -> [64][N] per head
    transpose_vc<<<dim3(DIM / 32, NSEQ / 32), dim3(32, 8)>>>(qh, ql, vth, vtl);

    // 2-4) panel score3: term1 / sig / Sc, A staged once per CTA, 4 n-tiles each
    score3_panel<<<dim3(4, 16, HEADS * 3), 256, SMTP>>>(
        qh, ql, sc, t1h, t1l, sgh, sgl);

    // 5) su = silu(term1 @ sig^T), triangular k-range (epi 6)
    mma_gemm<128, 2><<<dim3(16, 16, HEADS), 256, SMT128>>>(
        t1h, t1l, NSEQ, HSLL, sgh, sgl, NSEQ, HSLL,
        su, (bf16*)0, (bf16*)0, (bf16*)0, (bf16*)0, NSEQ, HSLL,
        NSEQ, 6, 1, 1, 0);

    // 6) softmax(sc - su) -> attn split pair (su already silu'd)
    softmax_kernel<<<dim3(NSEQ, HEADS), 256>>>(sc, su, ah, al, NSEQ);

    // 7) split-K attn@vc: partials into op[seg], balanced across 4 segments
    mma_gemm<64, 4><<<dim3(4, 16, HEADS), 256, SMT64>>>(
        ah, al, NSEQ, HSLL, vth, vtl, NSEQ, 64LL * NSEQ,
        op, (bf16*)0, (bf16*)0, (bf16*)0, (bf16*)0, DIM, 64,
        NSEQ, 0, 0, 3, 0);

    // 7b) reduce partials -> oh/ol split pair
    reduce_split<<<NSEQ * DIM / 512, 256>>>(op, oh, ol);

    // 8) out = o @ w_out^T, fp32
    mma_gemm<128, 2><<<dim3(DIM / 128, NSEQ / 128, 1), 256, SMT128>>>(
        oh, ol, HEADS * 64, 0, woh, wol, HEADS * 64, 0,
        out, (bf16*)0, (bf16*)0, (bf16*)0, (bf16*)0, DIM, 0,
        HEADS * 64, 0, 0, 0, 0);
}